// round 2
// baseline (speedup 1.0000x reference)
#include <cuda_runtime.h>

#define NN   131072
#define EE   2097152
#define FF   32
#define HH   128
#define RR   10
#define BB   4
#define LL   3
#define OUTD 8

// ---------------- device scratch (static allocation; no cudaMalloc) ----------------
__device__ float g_h  [(size_t)NN * HH];          // node features (67 MB)
__device__ float g_t  [(size_t)NN * HH];          // GEMM output / hidden (67 MB)
__device__ float g_a  [(size_t)NN * RR * HH];     // per-(dst,rel) aggregation (671 MB)
__device__ float g_ab [(size_t)NN * BB * HH];     // comp-folded aggregation (268 MB)
__device__ float g_cnt[NN * RR];
__device__ float g_inv[EE];
__device__ int   g_src[EE];
__device__ int   g_dst[EE];
__device__ int   g_et [EE];
__device__ int   g_is64;

// ---------------- dtype detect: int64 buffers have zero high words ----------------
__global__ void k_detect(const int* __restrict__ ei) {
    __shared__ int cnt;
    if (threadIdx.x == 0) cnt = 0;
    __syncthreads();
    // odd int32 words of the first 256 logical entries
    if (ei[threadIdx.x * 2 + 1] != 0) atomicAdd(&cnt, 1);
    __syncthreads();
    if (threadIdx.x == 0) g_is64 = (cnt == 0) ? 1 : 0;
}

// ---------------- prep: decode edge buffers (int32 or int64) ----------------
__global__ void k_prep(const void* __restrict__ ei_raw, const void* __restrict__ et_raw) {
    int e = blockIdx.x * blockDim.x + threadIdx.x;
    if (e >= EE) return;
    if (g_is64) {
        const long long* ei = (const long long*)ei_raw;
        const long long* et = (const long long*)et_raw;
        g_src[e] = (int)ei[e];
        g_dst[e] = (int)ei[(size_t)EE + e];
        g_et[e]  = (int)et[e];
    } else {
        const int* ei = (const int*)ei_raw;
        const int* et = (const int*)et_raw;
        g_src[e] = ei[e];
        g_dst[e] = ei[EE + e];
        g_et[e]  = et[e];
    }
}

__global__ void k_zero_cnt() {
    int i = blockIdx.x * blockDim.x + threadIdx.x;
    if (i < NN * RR) g_cnt[i] = 0.0f;
}

__global__ void k_count() {
    int e = blockIdx.x * blockDim.x + threadIdx.x;
    if (e >= EE) return;
    atomicAdd(&g_cnt[g_dst[e] * RR + g_et[e]], 1.0f);
}

__global__ void k_inv() {
    int e = blockIdx.x * blockDim.x + threadIdx.x;
    if (e >= EE) return;
    g_inv[e] = 1.0f / fmaxf(g_cnt[g_dst[e] * RR + g_et[e]], 1.0f);
}

// ---------------- input projection: h = x @ W_in + b_in ----------------
__global__ void k_inproj(const float* __restrict__ x, const float* __restrict__ W,
                         const float* __restrict__ b) {
    __shared__ float Ws[FF * HH];
    __shared__ float xs[8][FF];
    int tid = threadIdx.x;                 // 128 threads
    for (int i = tid; i < FF * HH; i += 128) Ws[i] = W[i];
    int n0 = blockIdx.x * 8;
    for (int i = tid; i < 8 * FF; i += 128) xs[i / FF][i % FF] = x[(size_t)n0 * FF + i];
    __syncthreads();
    float bj = b[tid];
#pragma unroll
    for (int u = 0; u < 8; u++) {
        float acc = bj;
#pragma unroll
        for (int k = 0; k < FF; k++) acc += xs[u][k] * Ws[k * HH + tid];
        g_h[(size_t)(n0 + u) * HH + tid] = acc;
    }
}

// ---------------- zero the big aggregation buffer ----------------
__global__ void k_zero_a() {
    size_t i = (size_t)blockIdx.x * blockDim.x + threadIdx.x;
    const size_t n4 = (size_t)NN * RR * HH / 4;
    if (i < n4) ((float4*)g_a)[i] = make_float4(0.f, 0.f, 0.f, 0.f);
}

// ---------------- edge scatter: a[dst, et] += inv * h[src]  (warp per edge) ----------------
__global__ void k_scatter() {
    int w    = (blockIdx.x * blockDim.x + threadIdx.x) >> 5;
    int lane = threadIdx.x & 31;
    if (w >= EE) return;
    int   s   = g_src[w];
    int   d   = g_dst[w];
    int   t   = g_et[w];
    float inv = g_inv[w];
    float4 v = ((const float4*)(g_h + (size_t)s * HH))[lane];
    float* ap = g_a + ((size_t)d * RR + t) * HH + lane * 4;
    atomicAdd(ap + 0, v.x * inv);
    atomicAdd(ap + 1, v.y * inv);
    atomicAdd(ap + 2, v.z * inv);
    atomicAdd(ap + 3, v.w * inv);
}

// ---------------- fold comp: a_b[n,b,:] = sum_r comp[r,b] * a[n,r,:] ----------------
__global__ void k_fold(const float* __restrict__ comp) {
    __shared__ float cs[RR * BB];
    if (threadIdx.x < RR * BB) cs[threadIdx.x] = comp[threadIdx.x];
    __syncthreads();
    int idx = blockIdx.x * blockDim.x + threadIdx.x;   // over NN*HH
    int n = idx >> 7, c = idx & 127;
    const float* ap = g_a + (size_t)n * (RR * HH) + c;
    float a0 = 0.f, a1 = 0.f, a2 = 0.f, a3 = 0.f;
#pragma unroll
    for (int r = 0; r < RR; r++) {
        float v = ap[(size_t)r * HH];
        a0 += v * cs[r * BB + 0];
        a1 += v * cs[r * BB + 1];
        a2 += v * cs[r * BB + 2];
        a3 += v * cs[r * BB + 3];
    }
    float* op = g_ab + (size_t)n * (BB * HH) + c;
    op[0 * HH] = a0; op[1 * HH] = a1; op[2 * HH] = a2; op[3 * HH] = a3;
}

// ---------------- fp32 GEMM: C = [A1 | A2] @ [B1 ; B2] + bias  (M=NN, Ncols=128) ----------------
// 128x128 block tile, 256 threads, 8x8 microtile, K-chunks of 16.
#define KC 16
#define SPAD 8
__global__ void __launch_bounds__(256) k_gemm(
    const float* __restrict__ A1, int lda1, int k1,
    const float* __restrict__ A2, int lda2, int k2,
    const float* __restrict__ B1, const float* __restrict__ B2,
    const float* __restrict__ bias, float* __restrict__ C, int relu)
{
    __shared__ float As[KC][HH + SPAD];
    __shared__ float Bs[KC][HH + SPAD];
    int tid = threadIdx.x;
    int m0  = blockIdx.x * 128;
    int tx = tid & 15, ty = tid >> 4;

    float acc[8][8];
#pragma unroll
    for (int i = 0; i < 8; i++)
#pragma unroll
        for (int j = 0; j < 8; j++) acc[i][j] = 0.f;

    float bv[8];
#pragma unroll
    for (int j = 0; j < 8; j++) bv[j] = bias[tx * 8 + j];

    const int K = k1 + k2;
    for (int kk = 0; kk < K; kk += KC) {
        const float* Ap; int ld; int kloc;
        if (kk < k1) { Ap = A1; ld = lda1; kloc = kk; }
        else         { Ap = A2; ld = lda2; kloc = kk - k1; }
#pragma unroll
        for (int p = 0; p < 2; p++) {
            int m  = (tid >> 2) + p * 64;
            int kq = (tid & 3) * 4;
            float4 v = *(const float4*)(Ap + (size_t)(m0 + m) * ld + kloc + kq);
            As[kq + 0][m] = v.x; As[kq + 1][m] = v.y;
            As[kq + 2][m] = v.z; As[kq + 3][m] = v.w;
        }
        const float* Bp = (kk < k1) ? (B1 + (size_t)kloc * HH) : (B2 + (size_t)kloc * HH);
#pragma unroll
        for (int p = 0; p < 2; p++) {
            int kr = (tid >> 5) + p * 8;
            int cc = (tid & 31) * 4;
            *(float4*)&Bs[kr][cc] = *(const float4*)(Bp + (size_t)kr * HH + cc);
        }
        __syncthreads();
#pragma unroll
        for (int k = 0; k < KC; k++) {
            float af[8], bf[8];
            *(float4*)(af)     = *(float4*)&As[k][ty * 8];
            *(float4*)(af + 4) = *(float4*)&As[k][ty * 8 + 4];
            *(float4*)(bf)     = *(float4*)&Bs[k][tx * 8];
            *(float4*)(bf + 4) = *(float4*)&Bs[k][tx * 8 + 4];
#pragma unroll
            for (int i = 0; i < 8; i++)
#pragma unroll
                for (int j = 0; j < 8; j++)
                    acc[i][j] += af[i] * bf[j];
        }
        __syncthreads();
    }

#pragma unroll
    for (int i = 0; i < 8; i++) {
        int row = m0 + ty * 8 + i;
#pragma unroll
        for (int j = 0; j < 8; j += 4) {
            float4 v;
            v.x = acc[i][j + 0] + bv[j + 0];
            v.y = acc[i][j + 1] + bv[j + 1];
            v.z = acc[i][j + 2] + bv[j + 2];
            v.w = acc[i][j + 3] + bv[j + 3];
            if (relu) {
                v.x = fmaxf(v.x, 0.f); v.y = fmaxf(v.y, 0.f);
                v.z = fmaxf(v.z, 0.f); v.w = fmaxf(v.w, 0.f);
            }
            *(float4*)(C + (size_t)row * HH + tx * 8 + j) = v;
        }
    }
}

// ---------------- LayerNorm + ReLU + optional residual; writes back into g_h ----------------
__global__ void k_ln(const float* __restrict__ gamma, const float* __restrict__ beta,
                     int residual) {
    int w    = (blockIdx.x * blockDim.x + threadIdx.x) >> 5;
    int lane = threadIdx.x & 31;
    if (w >= NN) return;
    float4 v = ((const float4*)(g_t + (size_t)w * HH))[lane];
    float s = v.x + v.y + v.z + v.w;
#pragma unroll
    for (int o = 16; o; o >>= 1) s += __shfl_xor_sync(0xFFFFFFFFu, s, o);
    float mu = s * (1.0f / HH);
    float dx = v.x - mu, dy = v.y - mu, dz = v.z - mu, dw = v.w - mu;
    float q = dx * dx + dy * dy + dz * dz + dw * dw;
#pragma unroll
    for (int o = 16; o; o >>= 1) q += __shfl_xor_sync(0xFFFFFFFFu, q, o);
    float rs = rsqrtf(q * (1.0f / HH) + 1e-5f);
    float4 g4 = ((const float4*)gamma)[lane];
    float4 b4 = ((const float4*)beta)[lane];
    float4 o4;
    o4.x = fmaxf(dx * rs * g4.x + b4.x, 0.f);
    o4.y = fmaxf(dy * rs * g4.y + b4.y, 0.f);
    o4.z = fmaxf(dz * rs * g4.z + b4.z, 0.f);
    o4.w = fmaxf(dw * rs * g4.w + b4.w, 0.f);
    if (residual) {
        float4 h4 = ((const float4*)(g_h + (size_t)w * HH))[lane];
        o4.x += h4.x; o4.y += h4.y; o4.z += h4.z; o4.w += h4.w;
    }
    ((float4*)(g_h + (size_t)w * HH))[lane] = o4;
}

// ---------------- head tail: out = hidden @ W2 + b2 ----------------
__global__ void k_head2(const float* __restrict__ W2, const float* __restrict__ b2,
                        float* __restrict__ out) {
    int idx = blockIdx.x * blockDim.x + threadIdx.x;
    if (idx >= NN * OUTD) return;
    int n = idx >> 3, o = idx & 7;
    const float* hp = g_t + (size_t)n * HH;
    float acc = b2[o];
#pragma unroll
    for (int k = 0; k < HH; k++) acc += hp[k] * W2[k * OUTD + o];
    out[idx] = acc;
}

// ---------------- launch ----------------
extern "C" void kernel_launch(void* const* d_in, const int* in_sizes, int n_in,
                              void* d_out, int out_size) {
    const float* x     = (const float*)d_in[0];
    const void*  ei    = d_in[1];
    const void*  et    = d_in[2];
    const float* W_in  = (const float*)d_in[3];
    const float* b_in  = (const float*)d_in[4];
    const float* basis = (const float*)d_in[5];
    const float* comp  = (const float*)d_in[6];
    const float* root  = (const float*)d_in[7];
    const float* bias  = (const float*)d_in[8];
    const float* ln_g  = (const float*)d_in[9];
    const float* ln_b  = (const float*)d_in[10];
    const float* W1    = (const float*)d_in[11];
    const float* b1    = (const float*)d_in[12];
    const float* W2    = (const float*)d_in[13];
    const float* b2    = (const float*)d_in[14];

    void *p_h, *p_t, *p_ab;
    cudaGetSymbolAddress(&p_h,  g_h);
    cudaGetSymbolAddress(&p_t,  g_t);
    cudaGetSymbolAddress(&p_ab, g_ab);

    k_detect<<<1, 256>>>((const int*)ei);
    k_prep<<<EE / 256, 256>>>(ei, et);
    k_zero_cnt<<<(NN * RR + 255) / 256, 256>>>();
    k_count<<<EE / 256, 256>>>();
    k_inv<<<EE / 256, 256>>>();
    k_inproj<<<NN / 8, 128>>>(x, W_in, b_in);

    for (int i = 0; i < LL; i++) {
        k_zero_a<<<(int)((size_t)NN * RR * HH / 4 / 256), 256>>>();
        k_scatter<<<EE / 8, 256>>>();
        k_fold<<<NN * HH / 256, 256>>>(comp + i * RR * BB);
        k_gemm<<<NN / 128, 256>>>((const float*)p_ab, BB * HH, BB * HH,
                                  (const float*)p_h, HH, HH,
                                  basis + (size_t)i * BB * HH * HH,
                                  root + (size_t)i * HH * HH,
                                  bias + i * HH, (float*)p_t, 0);
        k_ln<<<NN / 8, 256>>>(ln_g + i * HH, ln_b + i * HH, i > 0 ? 1 : 0);
    }

    // head: hidden = relu(h @ W1 + b1); out = hidden @ W2 + b2
    k_gemm<<<NN / 128, 256>>>((const float*)p_h, HH, HH,
                              (const float*)nullptr, 0, 0,
                              W1, (const float*)nullptr,
                              b1, (float*)p_t, 1);
    k_head2<<<NN * OUTD / 256, 256>>>(W2, b2, (float*)d_out);
}

// round 3
// speedup vs baseline: 1.9103x; 1.9103x over previous
#include <cuda_runtime.h>

#define NN   131072
#define EE   2097152
#define FF   32
#define HH   128
#define RR   10
#define BB   4
#define LL   3
#define OUTD 8

// ---------------- device scratch (static allocation; no cudaMalloc) ----------------
__device__ float g_h  [(size_t)NN * HH];          // node features (67 MB)
__device__ float g_t  [(size_t)NN * HH];          // GEMM output / hidden (67 MB)
__device__ float g_ab [(size_t)NN * BB * HH];     // folded aggregation (268 MB)
__device__ float g_cnt[NN * RR];                  // per-(dst,rel) in-degree
__device__ int   g_src[EE];
__device__ int   g_dst[EE];
__device__ int   g_et [EE];
__device__ int   g_deg[NN];                       // per-dst degree
__device__ int   g_row[NN + 1];                   // CSR row offsets
__device__ int   g_bsum[512];                     // scan partials
__device__ int   g_cursor[NN];                    // scatter cursors
__device__ int   g_spk[EE];                       // sorted packed (src | et<<20)
__device__ float g_sinv[EE];                      // sorted 1/cnt(dst,rel)
__device__ int   g_is64;

// ---------------- dtype detect: int64 buffers have zero high words ----------------
__global__ void k_detect(const int* __restrict__ ei) {
    __shared__ int cnt;
    if (threadIdx.x == 0) cnt = 0;
    __syncthreads();
    if (ei[threadIdx.x * 2 + 1] != 0) atomicAdd(&cnt, 1);
    __syncthreads();
    if (threadIdx.x == 0) g_is64 = (cnt == 0) ? 1 : 0;
}

// ---------------- prep: decode edge buffers (int32 or int64) ----------------
__global__ void k_prep(const void* __restrict__ ei_raw, const void* __restrict__ et_raw) {
    int e = blockIdx.x * blockDim.x + threadIdx.x;
    if (e >= EE) return;
    if (g_is64) {
        const long long* ei = (const long long*)ei_raw;
        const long long* et = (const long long*)et_raw;
        g_src[e] = (int)ei[e];
        g_dst[e] = (int)ei[(size_t)EE + e];
        g_et[e]  = (int)et[e];
    } else {
        const int* ei = (const int*)ei_raw;
        const int* et = (const int*)et_raw;
        g_src[e] = ei[e];
        g_dst[e] = ei[EE + e];
        g_et[e]  = et[e];
    }
}

__global__ void k_zero_cnt() {
    int i = blockIdx.x * blockDim.x + threadIdx.x;
    if (i < NN * RR) g_cnt[i] = 0.0f;
    if (i < NN) g_deg[i] = 0;
}

__global__ void k_count() {
    int e = blockIdx.x * blockDim.x + threadIdx.x;
    if (e >= EE) return;
    int d = g_dst[e];
    atomicAdd(&g_cnt[d * RR + g_et[e]], 1.0f);
    atomicAdd(&g_deg[d], 1);
}

// ---------------- 3-phase exclusive prefix scan of g_deg -> g_row ----------------
__global__ void k_ps1() {
    __shared__ int sh[256];
    int i = blockIdx.x * 256 + threadIdx.x;
    int v = g_deg[i];
    sh[threadIdx.x] = v;
    __syncthreads();
#pragma unroll
    for (int o = 1; o < 256; o <<= 1) {
        int t = (threadIdx.x >= o) ? sh[threadIdx.x - o] : 0;
        __syncthreads();
        sh[threadIdx.x] += t;
        __syncthreads();
    }
    g_row[i] = sh[threadIdx.x] - v;       // exclusive
    if (threadIdx.x == 255) g_bsum[blockIdx.x] = sh[255];
}

__global__ void k_ps2() {
    __shared__ int sh[512];
    int v = g_bsum[threadIdx.x];
    sh[threadIdx.x] = v;
    __syncthreads();
#pragma unroll
    for (int o = 1; o < 512; o <<= 1) {
        int t = (threadIdx.x >= o) ? sh[threadIdx.x - o] : 0;
        __syncthreads();
        sh[threadIdx.x] += t;
        __syncthreads();
    }
    g_bsum[threadIdx.x] = sh[threadIdx.x] - v;   // exclusive
}

__global__ void k_ps3() {
    int i = blockIdx.x * 256 + threadIdx.x;
    int r = g_row[i] + g_bsum[i >> 8];
    g_row[i] = r;
    g_cursor[i] = r;
    if (i == 0) g_row[NN] = EE;
}

// ---------------- CSR scatter: sorted packed metadata ----------------
__global__ void k_csr_scatter() {
    int e = blockIdx.x * blockDim.x + threadIdx.x;
    if (e >= EE) return;
    int d = g_dst[e];
    int t = g_et[e];
    int pos = atomicAdd(&g_cursor[d], 1);
    g_spk[pos]  = g_src[e] | (t << 20);
    g_sinv[pos] = 1.0f / fmaxf(g_cnt[d * RR + t], 1.0f);
}

// ---------------- input projection: h = x @ W_in + b_in ----------------
__global__ void k_inproj(const float* __restrict__ x, const float* __restrict__ W,
                         const float* __restrict__ b) {
    __shared__ float Ws[FF * HH];
    __shared__ float xs[8][FF];
    int tid = threadIdx.x;                 // 128 threads
    for (int i = tid; i < FF * HH; i += 128) Ws[i] = W[i];
    int n0 = blockIdx.x * 8;
    for (int i = tid; i < 8 * FF; i += 128) xs[i / FF][i % FF] = x[(size_t)n0 * FF + i];
    __syncthreads();
    float bj = b[tid];
#pragma unroll
    for (int u = 0; u < 8; u++) {
        float acc = bj;
#pragma unroll
        for (int k = 0; k < FF; k++) acc += xs[u][k] * Ws[k * HH + tid];
        g_h[(size_t)(n0 + u) * HH + tid] = acc;
    }
}

// ---------------- aggregation: warp per dst, register-resident folded accumulators ----------------
// a_b[dst,b,:] = sum_{e in edges(dst)} comp[et_e,b] * inv_e * h[src_e,:]
__global__ void __launch_bounds__(256) k_agg(const float* __restrict__ comp) {
    __shared__ float cs[RR * BB];
    if (threadIdx.x < RR * BB) cs[threadIdx.x] = comp[threadIdx.x];
    __syncthreads();
    int w    = (blockIdx.x * blockDim.x + threadIdx.x) >> 5;   // dst node
    int lane = threadIdx.x & 31;
    if (w >= NN) return;
    int beg = g_row[w], end = g_row[w + 1];

    float4 a0 = make_float4(0.f, 0.f, 0.f, 0.f);
    float4 a1 = a0, a2 = a0, a3 = a0;

    for (int e = beg; e < end; e++) {
        int   pk  = __ldg(&g_spk[e]);
        float inv = __ldg(&g_sinv[e]);
        int s = pk & 0xFFFFF;
        int t = pk >> 20;
        float c0 = cs[t * BB + 0] * inv;
        float c1 = cs[t * BB + 1] * inv;
        float c2 = cs[t * BB + 2] * inv;
        float c3 = cs[t * BB + 3] * inv;
        float4 v = __ldg(&((const float4*)(g_h + (size_t)s * HH))[lane]);
        a0.x += c0 * v.x; a0.y += c0 * v.y; a0.z += c0 * v.z; a0.w += c0 * v.w;
        a1.x += c1 * v.x; a1.y += c1 * v.y; a1.z += c1 * v.z; a1.w += c1 * v.w;
        a2.x += c2 * v.x; a2.y += c2 * v.y; a2.z += c2 * v.z; a2.w += c2 * v.w;
        a3.x += c3 * v.x; a3.y += c3 * v.y; a3.z += c3 * v.z; a3.w += c3 * v.w;
    }

    float4* op = (float4*)(g_ab + (size_t)w * (BB * HH));
    op[0 * 32 + lane] = a0;
    op[1 * 32 + lane] = a1;
    op[2 * 32 + lane] = a2;
    op[3 * 32 + lane] = a3;
}

// ---------------- fp32 GEMM: C = [A1 | A2] @ [B1 ; B2] + bias  (M=NN, Ncols=128) ----------------
#define KC 16
#define SPAD 8
__global__ void __launch_bounds__(256) k_gemm(
    const float* __restrict__ A1, int lda1, int k1,
    const float* __restrict__ A2, int lda2, int k2,
    const float* __restrict__ B1, const float* __restrict__ B2,
    const float* __restrict__ bias, float* __restrict__ C, int relu)
{
    __shared__ float As[KC][HH + SPAD];
    __shared__ float Bs[KC][HH + SPAD];
    int tid = threadIdx.x;
    int m0  = blockIdx.x * 128;
    int tx = tid & 15, ty = tid >> 4;

    float acc[8][8];
#pragma unroll
    for (int i = 0; i < 8; i++)
#pragma unroll
        for (int j = 0; j < 8; j++) acc[i][j] = 0.f;

    float bv[8];
#pragma unroll
    for (int j = 0; j < 8; j++) bv[j] = bias[tx * 8 + j];

    const int K = k1 + k2;
    for (int kk = 0; kk < K; kk += KC) {
        const float* Ap; int ld; int kloc;
        if (kk < k1) { Ap = A1; ld = lda1; kloc = kk; }
        else         { Ap = A2; ld = lda2; kloc = kk - k1; }
#pragma unroll
        for (int p = 0; p < 2; p++) {
            int m  = (tid >> 2) + p * 64;
            int kq = (tid & 3) * 4;
            float4 v = *(const float4*)(Ap + (size_t)(m0 + m) * ld + kloc + kq);
            As[kq + 0][m] = v.x; As[kq + 1][m] = v.y;
            As[kq + 2][m] = v.z; As[kq + 3][m] = v.w;
        }
        const float* Bp = (kk < k1) ? (B1 + (size_t)kloc * HH) : (B2 + (size_t)kloc * HH);
#pragma unroll
        for (int p = 0; p < 2; p++) {
            int kr = (tid >> 5) + p * 8;
            int cc = (tid & 31) * 4;
            *(float4*)&Bs[kr][cc] = *(const float4*)(Bp + (size_t)kr * HH + cc);
        }
        __syncthreads();
#pragma unroll
        for (int k = 0; k < KC; k++) {
            float af[8], bf[8];
            *(float4*)(af)     = *(float4*)&As[k][ty * 8];
            *(float4*)(af + 4) = *(float4*)&As[k][ty * 8 + 4];
            *(float4*)(bf)     = *(float4*)&Bs[k][tx * 8];
            *(float4*)(bf + 4) = *(float4*)&Bs[k][tx * 8 + 4];
#pragma unroll
            for (int i = 0; i < 8; i++)
#pragma unroll
                for (int j = 0; j < 8; j++)
                    acc[i][j] += af[i] * bf[j];
        }
        __syncthreads();
    }

#pragma unroll
    for (int i = 0; i < 8; i++) {
        int row = m0 + ty * 8 + i;
#pragma unroll
        for (int j = 0; j < 8; j += 4) {
            float4 v;
            v.x = acc[i][j + 0] + bv[j + 0];
            v.y = acc[i][j + 1] + bv[j + 1];
            v.z = acc[i][j + 2] + bv[j + 2];
            v.w = acc[i][j + 3] + bv[j + 3];
            if (relu) {
                v.x = fmaxf(v.x, 0.f); v.y = fmaxf(v.y, 0.f);
                v.z = fmaxf(v.z, 0.f); v.w = fmaxf(v.w, 0.f);
            }
            *(float4*)(C + (size_t)row * HH + tx * 8 + j) = v;
        }
    }
}

// ---------------- LayerNorm + ReLU + optional residual; writes back into g_h ----------------
__global__ void k_ln(const float* __restrict__ gamma, const float* __restrict__ beta,
                     int residual) {
    int w    = (blockIdx.x * blockDim.x + threadIdx.x) >> 5;
    int lane = threadIdx.x & 31;
    if (w >= NN) return;
    float4 v = ((const float4*)(g_t + (size_t)w * HH))[lane];
    float s = v.x + v.y + v.z + v.w;
#pragma unroll
    for (int o = 16; o; o >>= 1) s += __shfl_xor_sync(0xFFFFFFFFu, s, o);
    float mu = s * (1.0f / HH);
    float dx = v.x - mu, dy = v.y - mu, dz = v.z - mu, dw = v.w - mu;
    float q = dx * dx + dy * dy + dz * dz + dw * dw;
#pragma unroll
    for (int o = 16; o; o >>= 1) q += __shfl_xor_sync(0xFFFFFFFFu, q, o);
    float rs = rsqrtf(q * (1.0f / HH) + 1e-5f);
    float4 g4 = ((const float4*)gamma)[lane];
    float4 b4 = ((const float4*)beta)[lane];
    float4 o4;
    o4.x = fmaxf(dx * rs * g4.x + b4.x, 0.f);
    o4.y = fmaxf(dy * rs * g4.y + b4.y, 0.f);
    o4.z = fmaxf(dz * rs * g4.z + b4.z, 0.f);
    o4.w = fmaxf(dw * rs * g4.w + b4.w, 0.f);
    if (residual) {
        float4 h4 = ((const float4*)(g_h + (size_t)w * HH))[lane];
        o4.x += h4.x; o4.y += h4.y; o4.z += h4.z; o4.w += h4.w;
    }
    ((float4*)(g_h + (size_t)w * HH))[lane] = o4;
}

// ---------------- head tail: out = hidden @ W2 + b2 ----------------
__global__ void k_head2(const float* __restrict__ W2, const float* __restrict__ b2,
                        float* __restrict__ out) {
    int idx = blockIdx.x * blockDim.x + threadIdx.x;
    if (idx >= NN * OUTD) return;
    int n = idx >> 3, o = idx & 7;
    const float* hp = g_t + (size_t)n * HH;
    float acc = b2[o];
#pragma unroll
    for (int k = 0; k < HH; k++) acc += hp[k] * W2[k * OUTD + o];
    out[idx] = acc;
}

// ---------------- launch ----------------
extern "C" void kernel_launch(void* const* d_in, const int* in_sizes, int n_in,
                              void* d_out, int out_size) {
    const float* x     = (const float*)d_in[0];
    const void*  ei    = d_in[1];
    const void*  et    = d_in[2];
    const float* W_in  = (const float*)d_in[3];
    const float* b_in  = (const float*)d_in[4];
    const float* basis = (const float*)d_in[5];
    const float* comp  = (const float*)d_in[6];
    const float* root  = (const float*)d_in[7];
    const float* bias  = (const float*)d_in[8];
    const float* ln_g  = (const float*)d_in[9];
    const float* ln_b  = (const float*)d_in[10];
    const float* W1    = (const float*)d_in[11];
    const float* b1    = (const float*)d_in[12];
    const float* W2    = (const float*)d_in[13];
    const float* b2    = (const float*)d_in[14];

    void *p_h, *p_t, *p_ab;
    cudaGetSymbolAddress(&p_h,  g_h);
    cudaGetSymbolAddress(&p_t,  g_t);
    cudaGetSymbolAddress(&p_ab, g_ab);

    // ---- one-time graph preprocessing ----
    k_detect<<<1, 256>>>((const int*)ei);
    k_prep<<<EE / 256, 256>>>(ei, et);
    k_zero_cnt<<<(NN * RR + 255) / 256, 256>>>();
    k_count<<<EE / 256, 256>>>();
    k_ps1<<<NN / 256, 256>>>();
    k_ps2<<<1, 512>>>();
    k_ps3<<<NN / 256, 256>>>();
    k_csr_scatter<<<EE / 256, 256>>>();
    k_inproj<<<NN / 8, 128>>>(x, W_in, b_in);

    // ---- layers ----
    for (int i = 0; i < LL; i++) {
        k_agg<<<NN / 8, 256>>>(comp + i * RR * BB);
        k_gemm<<<NN / 128, 256>>>((const float*)p_ab, BB * HH, BB * HH,
                                  (const float*)p_h, HH, HH,
                                  basis + (size_t)i * BB * HH * HH,
                                  root + (size_t)i * HH * HH,
                                  bias + i * HH, (float*)p_t, 0);
        k_ln<<<NN / 8, 256>>>(ln_g + i * HH, ln_b + i * HH, i > 0 ? 1 : 0);
    }

    // ---- head ----
    k_gemm<<<NN / 128, 256>>>((const float*)p_h, HH, HH,
                              (const float*)nullptr, 0, 0,
                              W1, (const float*)nullptr,
                              b1, (float*)p_t, 1);
    k_head2<<<NN * OUTD / 256, 256>>>(W2, b2, (float*)d_out);
}

// round 4
// speedup vs baseline: 2.0916x; 1.0949x over previous
#include <cuda_runtime.h>
#include <cstdint>

#define NN   131072
#define EE   2097152
#define FF   32
#define HH   128
#define RR   10
#define BB   4
#define LL   3
#define OUTD 8

// ---------------- device scratch (static allocation; no cudaMalloc) ----------------
__device__ float g_h  [(size_t)NN * HH];          // node features (67 MB)
__device__ float g_t  [(size_t)NN * HH];          // GEMM output / hidden (67 MB)
__device__ float g_ab [(size_t)NN * BB * HH];     // folded aggregation (268 MB)
__device__ float g_cnt[NN * RR];                  // per-(dst,rel) in-degree
__device__ int   g_src[EE];
__device__ int   g_dst[EE];
__device__ int   g_et [EE];
__device__ int   g_deg[NN];                       // per-dst degree
__device__ int   g_row[NN + 1];                   // CSR row offsets
__device__ int   g_bsum[512];                     // scan partials
__device__ int   g_cursor[NN];                    // scatter cursors
__device__ int   g_spk[EE];                       // sorted packed (src | et<<20)
__device__ float g_sinv[EE];                      // sorted 1/cnt(dst,rel)
__device__ int   g_is64;

// ---------------- helpers ----------------
__device__ __forceinline__ float tf32r(float x) {
    uint32_t o;
    asm("cvt.rna.tf32.f32 %0, %1;" : "=r"(o) : "f"(x));
    return __uint_as_float(o);
}

__device__ __forceinline__ void mma_tf32(float& c0, float& c1, float& c2, float& c3,
                                         uint32_t a0, uint32_t a1, uint32_t a2, uint32_t a3,
                                         uint32_t b0, uint32_t b1) {
    asm volatile(
        "mma.sync.aligned.m16n8k8.row.col.f32.tf32.tf32.f32 "
        "{%0,%1,%2,%3}, {%4,%5,%6,%7}, {%8,%9}, {%0,%1,%2,%3};"
        : "+f"(c0), "+f"(c1), "+f"(c2), "+f"(c3)
        : "r"(a0), "r"(a1), "r"(a2), "r"(a3), "r"(b0), "r"(b1));
}

// ---------------- dtype detect: int64 buffers have zero high words ----------------
__global__ void k_detect(const int* __restrict__ ei) {
    __shared__ int cnt;
    if (threadIdx.x == 0) cnt = 0;
    __syncthreads();
    if (ei[threadIdx.x * 2 + 1] != 0) atomicAdd(&cnt, 1);
    __syncthreads();
    if (threadIdx.x == 0) g_is64 = (cnt == 0) ? 1 : 0;
}

// ---------------- prep: decode edge buffers (int32 or int64) ----------------
__global__ void k_prep(const void* __restrict__ ei_raw, const void* __restrict__ et_raw) {
    int e = blockIdx.x * blockDim.x + threadIdx.x;
    if (e >= EE) return;
    if (g_is64) {
        const long long* ei = (const long long*)ei_raw;
        const long long* et = (const long long*)et_raw;
        g_src[e] = (int)ei[e];
        g_dst[e] = (int)ei[(size_t)EE + e];
        g_et[e]  = (int)et[e];
    } else {
        const int* ei = (const int*)ei_raw;
        const int* et = (const int*)et_raw;
        g_src[e] = ei[e];
        g_dst[e] = ei[EE + e];
        g_et[e]  = et[e];
    }
}

__global__ void k_zero_cnt() {
    int i = blockIdx.x * blockDim.x + threadIdx.x;
    if (i < NN * RR) g_cnt[i] = 0.0f;
    if (i < NN) g_deg[i] = 0;
}

__global__ void k_count() {
    int e = blockIdx.x * blockDim.x + threadIdx.x;
    if (e >= EE) return;
    int d = g_dst[e];
    atomicAdd(&g_cnt[d * RR + g_et[e]], 1.0f);
    atomicAdd(&g_deg[d], 1);
}

// ---------------- 3-phase exclusive prefix scan of g_deg -> g_row ----------------
__global__ void k_ps1() {
    __shared__ int sh[256];
    int i = blockIdx.x * 256 + threadIdx.x;
    int v = g_deg[i];
    sh[threadIdx.x] = v;
    __syncthreads();
#pragma unroll
    for (int o = 1; o < 256; o <<= 1) {
        int t = (threadIdx.x >= o) ? sh[threadIdx.x - o] : 0;
        __syncthreads();
        sh[threadIdx.x] += t;
        __syncthreads();
    }
    g_row[i] = sh[threadIdx.x] - v;       // exclusive
    if (threadIdx.x == 255) g_bsum[blockIdx.x] = sh[255];
}

__global__ void k_ps2() {
    __shared__ int sh[512];
    int v = g_bsum[threadIdx.x];
    sh[threadIdx.x] = v;
    __syncthreads();
#pragma unroll
    for (int o = 1; o < 512; o <<= 1) {
        int t = (threadIdx.x >= o) ? sh[threadIdx.x - o] : 0;
        __syncthreads();
        sh[threadIdx.x] += t;
        __syncthreads();
    }
    g_bsum[threadIdx.x] = sh[threadIdx.x] - v;   // exclusive
}

__global__ void k_ps3() {
    int i = blockIdx.x * 256 + threadIdx.x;
    int r = g_row[i] + g_bsum[i >> 8];
    g_row[i] = r;
    g_cursor[i] = r;
    if (i == 0) g_row[NN] = EE;
}

// ---------------- CSR scatter: sorted packed metadata ----------------
__global__ void k_csr_scatter() {
    int e = blockIdx.x * blockDim.x + threadIdx.x;
    if (e >= EE) return;
    int d = g_dst[e];
    int t = g_et[e];
    int pos = atomicAdd(&g_cursor[d], 1);
    g_spk[pos]  = g_src[e] | (t << 20);
    g_sinv[pos] = 1.0f / fmaxf(g_cnt[d * RR + t], 1.0f);
}

// ---------------- input projection: h = x @ W_in + b_in ----------------
__global__ void k_inproj(const float* __restrict__ x, const float* __restrict__ W,
                         const float* __restrict__ b) {
    __shared__ float Ws[FF * HH];
    __shared__ float xs[8][FF];
    int tid = threadIdx.x;                 // 128 threads
    for (int i = tid; i < FF * HH; i += 128) Ws[i] = W[i];
    int n0 = blockIdx.x * 8;
    for (int i = tid; i < 8 * FF; i += 128) xs[i / FF][i % FF] = x[(size_t)n0 * FF + i];
    __syncthreads();
    float bj = b[tid];
#pragma unroll
    for (int u = 0; u < 8; u++) {
        float acc = bj;
#pragma unroll
        for (int k = 0; k < FF; k++) acc += xs[u][k] * Ws[k * HH + tid];
        g_h[(size_t)(n0 + u) * HH + tid] = acc;
    }
}

// ---------------- aggregation: warp per dst, register-resident folded accumulators ----------------
__global__ void __launch_bounds__(256) k_agg(const float* __restrict__ comp) {
    __shared__ float cs[RR * BB];
    if (threadIdx.x < RR * BB) cs[threadIdx.x] = comp[threadIdx.x];
    __syncthreads();
    int w    = (blockIdx.x * blockDim.x + threadIdx.x) >> 5;   // dst node
    int lane = threadIdx.x & 31;
    if (w >= NN) return;
    int beg = g_row[w], end = g_row[w + 1];

    float4 a0 = make_float4(0.f, 0.f, 0.f, 0.f);
    float4 a1 = a0, a2 = a0, a3 = a0;

    for (int e = beg; e < end; e++) {
        int   pk  = __ldg(&g_spk[e]);
        float inv = __ldg(&g_sinv[e]);
        int s = pk & 0xFFFFF;
        int t = pk >> 20;
        float c0 = cs[t * BB + 0] * inv;
        float c1 = cs[t * BB + 1] * inv;
        float c2 = cs[t * BB + 2] * inv;
        float c3 = cs[t * BB + 3] * inv;
        float4 v = __ldg(&((const float4*)(g_h + (size_t)s * HH))[lane]);
        a0.x += c0 * v.x; a0.y += c0 * v.y; a0.z += c0 * v.z; a0.w += c0 * v.w;
        a1.x += c1 * v.x; a1.y += c1 * v.y; a1.z += c1 * v.z; a1.w += c1 * v.w;
        a2.x += c2 * v.x; a2.y += c2 * v.y; a2.z += c2 * v.z; a2.w += c2 * v.w;
        a3.x += c3 * v.x; a3.y += c3 * v.y; a3.z += c3 * v.z; a3.w += c3 * v.w;
    }

    float4* op = (float4*)(g_ab + (size_t)w * (BB * HH));
    op[0 * 32 + lane] = a0;
    op[1 * 32 + lane] = a1;
    op[2 * 32 + lane] = a2;
    op[3 * 32 + lane] = a3;
}

// ---------------- 3xTF32 tensor-core GEMM: C = [A1 | A2] @ [B1 ; B2] + bias ----------------
// M=NN (tiled 128), Ncols=128 fixed. 8 warps (2m x 4n), warp tile 64x32,
// mma.m16n8k8 tf32 with hi/lo split (hi*hi + hi*lo + lo*hi) for fp32-like accuracy.
#define KC   16
#define LDSA 136   // (128 + 8) stride: conflict-free fragment loads
__global__ void __launch_bounds__(256) k_gemm(
    const float* __restrict__ A1, int lda1, int k1,
    const float* __restrict__ A2, int lda2, int k2,
    const float* __restrict__ B1, const float* __restrict__ B2,
    const float* __restrict__ bias, float* __restrict__ C, int relu)
{
    __shared__ float Ah[KC][LDSA], Al[KC][LDSA];
    __shared__ float Bh[KC][LDSA], Bl[KC][LDSA];

    int tid  = threadIdx.x;
    int warp = tid >> 5, lane = tid & 31;
    int wm = warp & 1, wn = warp >> 1;          // 2 x 4 warp grid
    int g  = lane >> 2, t = lane & 3;           // mma fragment coords
    int m0 = blockIdx.x * 128;

    float acc[4][4][4];                          // [mi][ni][c0..c3]
#pragma unroll
    for (int i = 0; i < 4; i++)
#pragma unroll
        for (int j = 0; j < 4; j++)
#pragma unroll
            for (int c = 0; c < 4; c++) acc[i][j][c] = 0.f;

    const int K = k1 + k2;
    for (int kk = 0; kk < K; kk += KC) {
        // ---- load A chunk: 128 rows x KC, store k-major hi/lo ----
        const float* Ap; int ld; int kloc;
        if (kk < k1) { Ap = A1; ld = lda1; kloc = kk; }
        else         { Ap = A2; ld = lda2; kloc = kk - k1; }
        {
            int m   = tid >> 1;
            int kq0 = (tid & 1) * 8;
#pragma unroll
            for (int q = 0; q < 2; q++) {
                float4 v = *(const float4*)(Ap + (size_t)(m0 + m) * ld + kloc + kq0 + q * 4);
                float e[4] = {v.x, v.y, v.z, v.w};
#pragma unroll
                for (int u = 0; u < 4; u++) {
                    float hi = tf32r(e[u]);
                    Ah[kq0 + q * 4 + u][m] = hi;
                    Al[kq0 + q * 4 + u][m] = tf32r(e[u] - hi);
                }
            }
        }
        // ---- load B chunk: KC rows x 128, hi/lo ----
        {
            const float* Bp = (kk < k1) ? (B1 + (size_t)kloc * HH) : (B2 + (size_t)(kk - k1) * HH);
            int kr  = tid >> 4;
            int cc0 = (tid & 15) * 8;
#pragma unroll
            for (int q = 0; q < 2; q++) {
                float4 v = *(const float4*)(Bp + (size_t)kr * HH + cc0 + q * 4);
                float e[4] = {v.x, v.y, v.z, v.w};
#pragma unroll
                for (int u = 0; u < 4; u++) {
                    float hi = tf32r(e[u]);
                    Bh[kr][cc0 + q * 4 + u] = hi;
                    Bl[kr][cc0 + q * 4 + u] = tf32r(e[u] - hi);
                }
            }
        }
        __syncthreads();

#pragma unroll
        for (int ks = 0; ks < KC / 8; ks++) {
            int k0 = ks * 8;
            uint32_t bh[4][2], bl[4][2];
#pragma unroll
            for (int ni = 0; ni < 4; ni++) {
                int nb = wn * 32 + ni * 8 + g;
                bh[ni][0] = __float_as_uint(Bh[k0 + t    ][nb]);
                bh[ni][1] = __float_as_uint(Bh[k0 + t + 4][nb]);
                bl[ni][0] = __float_as_uint(Bl[k0 + t    ][nb]);
                bl[ni][1] = __float_as_uint(Bl[k0 + t + 4][nb]);
            }
#pragma unroll
            for (int mi = 0; mi < 4; mi++) {
                int R = wm * 64 + mi * 16 + g;
                uint32_t ah0 = __float_as_uint(Ah[k0 + t    ][R]);
                uint32_t ah1 = __float_as_uint(Ah[k0 + t    ][R + 8]);
                uint32_t ah2 = __float_as_uint(Ah[k0 + t + 4][R]);
                uint32_t ah3 = __float_as_uint(Ah[k0 + t + 4][R + 8]);
                uint32_t al0 = __float_as_uint(Al[k0 + t    ][R]);
                uint32_t al1 = __float_as_uint(Al[k0 + t    ][R + 8]);
                uint32_t al2 = __float_as_uint(Al[k0 + t + 4][R]);
                uint32_t al3 = __float_as_uint(Al[k0 + t + 4][R + 8]);
#pragma unroll
                for (int ni = 0; ni < 4; ni++) {
                    float* c = acc[mi][ni];
                    mma_tf32(c[0], c[1], c[2], c[3], ah0, ah1, ah2, ah3, bh[ni][0], bh[ni][1]);
                    mma_tf32(c[0], c[1], c[2], c[3], ah0, ah1, ah2, ah3, bl[ni][0], bl[ni][1]);
                    mma_tf32(c[0], c[1], c[2], c[3], al0, al1, al2, al3, bh[ni][0], bh[ni][1]);
                }
            }
        }
        __syncthreads();
    }

    // ---- epilogue: bias (+relu), write C ----
#pragma unroll
    for (int ni = 0; ni < 4; ni++) {
        int col = wn * 32 + ni * 8 + 2 * t;
        float b0 = bias[col], b1 = bias[col + 1];
#pragma unroll
        for (int mi = 0; mi < 4; mi++) {
            int r0 = m0 + wm * 64 + mi * 16 + g;
            float* c = acc[mi][ni];
            float2 v0 = make_float2(c[0] + b0, c[1] + b1);
            float2 v1 = make_float2(c[2] + b0, c[3] + b1);
            if (relu) {
                v0.x = fmaxf(v0.x, 0.f); v0.y = fmaxf(v0.y, 0.f);
                v1.x = fmaxf(v1.x, 0.f); v1.y = fmaxf(v1.y, 0.f);
            }
            *(float2*)(C + (size_t)r0 * HH + col)       = v0;
            *(float2*)(C + (size_t)(r0 + 8) * HH + col) = v1;
        }
    }
}

// ---------------- LayerNorm + ReLU + optional residual; writes back into g_h ----------------
__global__ void k_ln(const float* __restrict__ gamma, const float* __restrict__ beta,
                     int residual) {
    int w    = (blockIdx.x * blockDim.x + threadIdx.x) >> 5;
    int lane = threadIdx.x & 31;
    if (w >= NN) return;
    float4 v = ((const float4*)(g_t + (size_t)w * HH))[lane];
    float s = v.x + v.y + v.z + v.w;
#pragma unroll
    for (int o = 16; o; o >>= 1) s += __shfl_xor_sync(0xFFFFFFFFu, s, o);
    float mu = s * (1.0f / HH);
    float dx = v.x - mu, dy = v.y - mu, dz = v.z - mu, dw = v.w - mu;
    float q = dx * dx + dy * dy + dz * dz + dw * dw;
#pragma unroll
    for (int o = 16; o; o >>= 1) q += __shfl_xor_sync(0xFFFFFFFFu, q, o);
    float rs = rsqrtf(q * (1.0f / HH) + 1e-5f);
    float4 g4 = ((const float4*)gamma)[lane];
    float4 b4 = ((const float4*)beta)[lane];
    float4 o4;
    o4.x = fmaxf(dx * rs * g4.x + b4.x, 0.f);
    o4.y = fmaxf(dy * rs * g4.y + b4.y, 0.f);
    o4.z = fmaxf(dz * rs * g4.z + b4.z, 0.f);
    o4.w = fmaxf(dw * rs * g4.w + b4.w, 0.f);
    if (residual) {
        float4 h4 = ((const float4*)(g_h + (size_t)w * HH))[lane];
        o4.x += h4.x; o4.y += h4.y; o4.z += h4.z; o4.w += h4.w;
    }
    ((float4*)(g_h + (size_t)w * HH))[lane] = o4;
}

// ---------------- head tail: out = hidden @ W2 + b2 ----------------
__global__ void k_head2(const float* __restrict__ W2, const float* __restrict__ b2,
                        float* __restrict__ out) {
    int idx = blockIdx.x * blockDim.x + threadIdx.x;
    if (idx >= NN * OUTD) return;
    int n = idx >> 3, o = idx & 7;
    const float* hp = g_t + (size_t)n * HH;
    float acc = b2[o];
#pragma unroll
    for (int k = 0; k < HH; k++) acc += hp[k] * W2[k * OUTD + o];
    out[idx] = acc;
}

// ---------------- launch ----------------
extern "C" void kernel_launch(void* const* d_in, const int* in_sizes, int n_in,
                              void* d_out, int out_size) {
    const float* x     = (const float*)d_in[0];
    const void*  ei    = d_in[1];
    const void*  et    = d_in[2];
    const float* W_in  = (const float*)d_in[3];
    const float* b_in  = (const float*)d_in[4];
    const float* basis = (const float*)d_in[5];
    const float* comp  = (const float*)d_in[6];
    const float* root  = (const float*)d_in[7];
    const float* bias  = (const float*)d_in[8];
    const float* ln_g  = (const float*)d_in[9];
    const float* ln_b  = (const float*)d_in[10];
    const float* W1    = (const float*)d_in[11];
    const float* b1    = (const float*)d_in[12];
    const float* W2    = (const float*)d_in[13];
    const float* b2    = (const float*)d_in[14];

    void *p_h, *p_t, *p_ab;
    cudaGetSymbolAddress(&p_h,  g_h);
    cudaGetSymbolAddress(&p_t,  g_t);
    cudaGetSymbolAddress(&p_ab, g_ab);

    // ---- one-time graph preprocessing ----
    k_detect<<<1, 256>>>((const int*)ei);
    k_prep<<<EE / 256, 256>>>(ei, et);
    k_zero_cnt<<<(NN * RR + 255) / 256, 256>>>();
    k_count<<<EE / 256, 256>>>();
    k_ps1<<<NN / 256, 256>>>();
    k_ps2<<<1, 512>>>();
    k_ps3<<<NN / 256, 256>>>();
    k_csr_scatter<<<EE / 256, 256>>>();
    k_inproj<<<NN / 8, 128>>>(x, W_in, b_in);

    // ---- layers ----
    for (int i = 0; i < LL; i++) {
        k_agg<<<NN / 8, 256>>>(comp + i * RR * BB);
        k_gemm<<<NN / 128, 256>>>((const float*)p_ab, BB * HH, BB * HH,
                                  (const float*)p_h, HH, HH,
                                  basis + (size_t)i * BB * HH * HH,
                                  root + (size_t)i * HH * HH,
                                  bias + i * HH, (float*)p_t, 0);
        k_ln<<<NN / 8, 256>>>(ln_g + i * HH, ln_b + i * HH, i > 0 ? 1 : 0);
    }

    // ---- head ----
    k_gemm<<<NN / 128, 256>>>((const float*)p_h, HH, HH,
                              (const float*)nullptr, 0, 0,
                              W1, (const float*)nullptr,
                              b1, (float*)p_t, 1);
    k_head2<<<NN * OUTD / 256, 256>>>(W2, b2, (float*)d_out);
}

// round 5
// speedup vs baseline: 2.9330x; 1.4023x over previous
#include <cuda_runtime.h>
#include <cuda_fp16.h>
#include <cstdint>

#define NN   131072
#define EE   2097152
#define FF   32
#define HH   128
#define RR   10
#define BB   4
#define LL   3
#define OUTD 8

#define TM   64               // fused-kernel block rows (dst nodes)
#define SAP  648              // sA k-stride in halves (640 + 8 pad -> stride ≡4 mod 32 words)
#define SBP  26               // sB row stride in halves
#define SB_BUF (128 * SBP)    // halves per B buffer
#define SCP  132              // sC row stride in floats
#define SMEM_LAYER (TM * SAP * 2 + 2 * SB_BUF * 2)   // 82944 + 13312 = 96256 B

// ---------------- device scratch ----------------
__device__ float g_h  [(size_t)NN * HH];
__device__ float g_t  [(size_t)NN * HH];
__device__ float g_cnt[NN * RR];
__device__ int   g_src[EE];
__device__ int   g_dst[EE];
__device__ int   g_et [EE];
__device__ int   g_deg[NN];
__device__ int   g_row[NN + 1];
__device__ int   g_bsum[512];
__device__ int   g_cursor[NN];
__device__ int   g_spk[EE];
__device__ float g_sinv[EE];
__device__ int   g_is64;

// ---------------- helpers ----------------
__device__ __forceinline__ float tf32r(float x) {
    uint32_t o;
    asm("cvt.rna.tf32.f32 %0, %1;" : "=r"(o) : "f"(x));
    return __uint_as_float(o);
}

__device__ __forceinline__ void mma_tf32(float& c0, float& c1, float& c2, float& c3,
                                         uint32_t a0, uint32_t a1, uint32_t a2, uint32_t a3,
                                         uint32_t b0, uint32_t b1) {
    asm volatile(
        "mma.sync.aligned.m16n8k8.row.col.f32.tf32.tf32.f32 "
        "{%0,%1,%2,%3}, {%4,%5,%6,%7}, {%8,%9}, {%0,%1,%2,%3};"
        : "+f"(c0), "+f"(c1), "+f"(c2), "+f"(c3)
        : "r"(a0), "r"(a1), "r"(a2), "r"(a3), "r"(b0), "r"(b1));
}

__device__ __forceinline__ void mma_f16(float* c,
                                        uint32_t a0, uint32_t a1, uint32_t a2, uint32_t a3,
                                        uint32_t b0, uint32_t b1) {
    asm volatile(
        "mma.sync.aligned.m16n8k16.row.col.f32.f16.f16.f32 "
        "{%0,%1,%2,%3}, {%4,%5,%6,%7}, {%8,%9}, {%0,%1,%2,%3};"
        : "+f"(c[0]), "+f"(c[1]), "+f"(c[2]), "+f"(c[3])
        : "r"(a0), "r"(a1), "r"(a2), "r"(a3), "r"(b0), "r"(b1));
}

// ---------------- dtype detect ----------------
__global__ void k_detect(const int* __restrict__ ei) {
    __shared__ int cnt;
    if (threadIdx.x == 0) cnt = 0;
    __syncthreads();
    if (ei[threadIdx.x * 2 + 1] != 0) atomicAdd(&cnt, 1);
    __syncthreads();
    if (threadIdx.x == 0) g_is64 = (cnt == 0) ? 1 : 0;
}

// ---------------- prep: decode edge buffers ----------------
__global__ void k_prep(const void* __restrict__ ei_raw, const void* __restrict__ et_raw) {
    int e = blockIdx.x * blockDim.x + threadIdx.x;
    if (e >= EE) return;
    if (g_is64) {
        const long long* ei = (const long long*)ei_raw;
        const long long* et = (const long long*)et_raw;
        g_src[e] = (int)ei[e];
        g_dst[e] = (int)ei[(size_t)EE + e];
        g_et[e]  = (int)et[e];
    } else {
        const int* ei = (const int*)ei_raw;
        const int* et = (const int*)et_raw;
        g_src[e] = ei[e];
        g_dst[e] = ei[EE + e];
        g_et[e]  = et[e];
    }
}

__global__ void k_zero_cnt() {
    int i = blockIdx.x * blockDim.x + threadIdx.x;
    if (i < NN * RR) g_cnt[i] = 0.0f;
    if (i < NN) g_deg[i] = 0;
}

__global__ void k_count() {
    int e = blockIdx.x * blockDim.x + threadIdx.x;
    if (e >= EE) return;
    int d = g_dst[e];
    atomicAdd(&g_cnt[d * RR + g_et[e]], 1.0f);
    atomicAdd(&g_deg[d], 1);
}

// ---------------- prefix scan ----------------
__global__ void k_ps1() {
    __shared__ int sh[256];
    int i = blockIdx.x * 256 + threadIdx.x;
    int v = g_deg[i];
    sh[threadIdx.x] = v;
    __syncthreads();
#pragma unroll
    for (int o = 1; o < 256; o <<= 1) {
        int t = (threadIdx.x >= o) ? sh[threadIdx.x - o] : 0;
        __syncthreads();
        sh[threadIdx.x] += t;
        __syncthreads();
    }
    g_row[i] = sh[threadIdx.x] - v;
    if (threadIdx.x == 255) g_bsum[blockIdx.x] = sh[255];
}

__global__ void k_ps2() {
    __shared__ int sh[512];
    int v = g_bsum[threadIdx.x];
    sh[threadIdx.x] = v;
    __syncthreads();
#pragma unroll
    for (int o = 1; o < 512; o <<= 1) {
        int t = (threadIdx.x >= o) ? sh[threadIdx.x - o] : 0;
        __syncthreads();
        sh[threadIdx.x] += t;
        __syncthreads();
    }
    g_bsum[threadIdx.x] = sh[threadIdx.x] - v;
}

__global__ void k_ps3() {
    int i = blockIdx.x * 256 + threadIdx.x;
    int r = g_row[i] + g_bsum[i >> 8];
    g_row[i] = r;
    g_cursor[i] = r;
    if (i == 0) g_row[NN] = EE;
}

// ---------------- CSR scatter ----------------
__global__ void k_csr_scatter() {
    int e = blockIdx.x * blockDim.x + threadIdx.x;
    if (e >= EE) return;
    int d = g_dst[e];
    int t = g_et[e];
    int pos = atomicAdd(&g_cursor[d], 1);
    g_spk[pos]  = g_src[e] | (t << 20);
    g_sinv[pos] = 1.0f / fmaxf(g_cnt[d * RR + t], 1.0f);
}

// ---------------- input projection ----------------
__global__ void k_inproj(const float* __restrict__ x, const float* __restrict__ W,
                         const float* __restrict__ b) {
    __shared__ float Ws[FF * HH];
    __shared__ float xs[8][FF];
    int tid = threadIdx.x;
    for (int i = tid; i < FF * HH; i += 128) Ws[i] = W[i];
    int n0 = blockIdx.x * 8;
    for (int i = tid; i < 8 * FF; i += 128) xs[i / FF][i % FF] = x[(size_t)n0 * FF + i];
    __syncthreads();
    float bj = b[tid];
#pragma unroll
    for (int u = 0; u < 8; u++) {
        float acc = bj;
#pragma unroll
        for (int k = 0; k < FF; k++) acc += xs[u][k] * Ws[k * HH + tid];
        g_h[(size_t)(n0 + u) * HH + tid] = acc;
    }
}

// ================= fused RGCN layer =================
// Per block: 64 dst nodes. Phase 1: stage h fp16 + aggregate a_b (fp32 regs -> fp16 smem).
// Phase 2: fp16 mma GEMM [64 x 640] @ [640 x 128]. Phase 3: bias + LN + relu + residual.
__global__ void __launch_bounds__(256, 2) k_layer(
    const float* __restrict__ in, float* __restrict__ out,
    const float* __restrict__ comp_l, const float* __restrict__ basis_l,
    const float* __restrict__ root_l, const float* __restrict__ bias_l,
    const float* __restrict__ gam, const float* __restrict__ bet, int residual)
{
    extern __shared__ __align__(16) char dyn[];
    __half* sA = (__half*)dyn;                       // [TM][SAP] k-cols
    __half* sB = (__half*)(dyn + TM * SAP * 2);      // 2 x [128][SBP]
    float*  sC = (float*)dyn;                        // epilogue reuse [TM][SCP]
    __shared__ float s_comp[RR * BB];

    int tid = threadIdx.x, warp = tid >> 5, lane = tid & 31;
    int m0 = blockIdx.x * TM;
    if (tid < RR * BB) s_comp[tid] = comp_l[tid];

    // ---- stage h (root-term planes 512..639) as fp16 ----
    for (int i = tid; i < TM * HH; i += 256) {
        int m = i >> 7, c = i & 127;
        sA[m * SAP + 512 + c] = __float2half_rn(in[(size_t)(m0 + m) * HH + c]);
    }
    __syncthreads();

    // ---- aggregation: 8 nodes per warp, fp32 reg accumulators ----
    for (int ii = 0; ii < 8; ii++) {
        int m = warp * 8 + ii;
        int node = m0 + m;
        int beg = g_row[node], end = g_row[node + 1];
        float4 a0 = make_float4(0.f, 0.f, 0.f, 0.f);
        float4 a1 = a0, a2 = a0, a3 = a0;
        for (int e = beg; e < end; e++) {
            int   pk  = __ldg(&g_spk[e]);
            float inv = __ldg(&g_sinv[e]);
            int s = pk & 0xFFFFF;
            int t = pk >> 20;
            float c0 = s_comp[t * BB + 0] * inv;
            float c1 = s_comp[t * BB + 1] * inv;
            float c2 = s_comp[t * BB + 2] * inv;
            float c3 = s_comp[t * BB + 3] * inv;
            float4 v = __ldg(&((const float4*)(in + (size_t)s * HH))[lane]);
            a0.x += c0 * v.x; a0.y += c0 * v.y; a0.z += c0 * v.z; a0.w += c0 * v.w;
            a1.x += c1 * v.x; a1.y += c1 * v.y; a1.z += c1 * v.z; a1.w += c1 * v.w;
            a2.x += c2 * v.x; a2.y += c2 * v.y; a2.z += c2 * v.z; a2.w += c2 * v.w;
            a3.x += c3 * v.x; a3.y += c3 * v.y; a3.z += c3 * v.z; a3.w += c3 * v.w;
        }
        __half* dst = sA + m * SAP + 4 * lane;
        *(__half2*)(dst + 0 * 128 + 0) = __floats2half2_rn(a0.x, a0.y);
        *(__half2*)(dst + 0 * 128 + 2) = __floats2half2_rn(a0.z, a0.w);
        *(__half2*)(dst + 1 * 128 + 0) = __floats2half2_rn(a1.x, a1.y);
        *(__half2*)(dst + 1 * 128 + 2) = __floats2half2_rn(a1.z, a1.w);
        *(__half2*)(dst + 2 * 128 + 0) = __floats2half2_rn(a2.x, a2.y);
        *(__half2*)(dst + 2 * 128 + 2) = __floats2half2_rn(a2.z, a2.w);
        *(__half2*)(dst + 3 * 128 + 0) = __floats2half2_rn(a3.x, a3.y);
        *(__half2*)(dst + 3 * 128 + 2) = __floats2half2_rn(a3.z, a3.w);
    }
    __syncthreads();

    // ---- GEMM: [TM x 640] @ [640 x 128], fp16 mma, 2m x 4n warp grid ----
    int wm = warp & 1, wn = warp >> 1;
    int g = lane >> 2, t = lane & 3;
    float acc[2][4][4];
#pragma unroll
    for (int i = 0; i < 2; i++)
#pragma unroll
        for (int j = 0; j < 4; j++)
#pragma unroll
            for (int c = 0; c < 4; c++) acc[i][j][c] = 0.f;

    int kr  = tid >> 4;              // 0..15
    int c0b = (tid & 15) * 8;        // 0..120
    float4 pb0, pb1;

    // prologue: chunk 0 (always basis)
    {
        const float* bp = basis_l + (size_t)kr * HH;
        pb0 = *(const float4*)(bp + c0b);
        pb1 = *(const float4*)(bp + c0b + 4);
        __half* d = sB + 0;
        d[(c0b + 0) * SBP + kr] = __float2half_rn(pb0.x);
        d[(c0b + 1) * SBP + kr] = __float2half_rn(pb0.y);
        d[(c0b + 2) * SBP + kr] = __float2half_rn(pb0.z);
        d[(c0b + 3) * SBP + kr] = __float2half_rn(pb0.w);
        d[(c0b + 4) * SBP + kr] = __float2half_rn(pb1.x);
        d[(c0b + 5) * SBP + kr] = __float2half_rn(pb1.y);
        d[(c0b + 6) * SBP + kr] = __float2half_rn(pb1.z);
        d[(c0b + 7) * SBP + kr] = __float2half_rn(pb1.w);
    }
    __syncthreads();

    for (int kc = 0; kc < 40; kc++) {
        if (kc < 39) {
            int kg = (kc + 1) * 16 + kr;
            const float* bp = (kg < 512) ? basis_l + (size_t)kg * HH
                                         : root_l + (size_t)(kg - 512) * HH;
            pb0 = *(const float4*)(bp + c0b);
            pb1 = *(const float4*)(bp + c0b + 4);
        }
        const __half* bb = sB + (kc & 1) * SB_BUF;
        int ka = kc * 16 + 2 * t;
        uint32_t Bf[4][2];
#pragma unroll
        for (int ni = 0; ni < 4; ni++) {
            int n = wn * 32 + ni * 8 + g;
            Bf[ni][0] = *(const uint32_t*)&bb[n * SBP + 2 * t];
            Bf[ni][1] = *(const uint32_t*)&bb[n * SBP + 2 * t + 8];
        }
#pragma unroll
        for (int mi = 0; mi < 2; mi++) {
            int R = wm * 32 + mi * 16 + g;
            uint32_t A0 = *(const uint32_t*)&sA[R * SAP + ka];
            uint32_t A1 = *(const uint32_t*)&sA[(R + 8) * SAP + ka];
            uint32_t A2 = *(const uint32_t*)&sA[R * SAP + ka + 8];
            uint32_t A3 = *(const uint32_t*)&sA[(R + 8) * SAP + ka + 8];
#pragma unroll
            for (int ni = 0; ni < 4; ni++)
                mma_f16(acc[mi][ni], A0, A1, A2, A3, Bf[ni][0], Bf[ni][1]);
        }
        if (kc < 39) {
            __half* d = sB + ((kc + 1) & 1) * SB_BUF;
            d[(c0b + 0) * SBP + kr] = __float2half_rn(pb0.x);
            d[(c0b + 1) * SBP + kr] = __float2half_rn(pb0.y);
            d[(c0b + 2) * SBP + kr] = __float2half_rn(pb0.z);
            d[(c0b + 3) * SBP + kr] = __float2half_rn(pb0.w);
            d[(c0b + 4) * SBP + kr] = __float2half_rn(pb1.x);
            d[(c0b + 5) * SBP + kr] = __float2half_rn(pb1.y);
            d[(c0b + 6) * SBP + kr] = __float2half_rn(pb1.z);
            d[(c0b + 7) * SBP + kr] = __float2half_rn(pb1.w);
        }
        __syncthreads();
    }

    // ---- epilogue: stage C to smem (reuses sA region; all sA reads done) ----
#pragma unroll
    for (int mi = 0; mi < 2; mi++) {
        int R = wm * 32 + mi * 16 + g;
#pragma unroll
        for (int ni = 0; ni < 4; ni++) {
            int col = wn * 32 + ni * 8 + 2 * t;
            sC[R * SCP + col]           = acc[mi][ni][0];
            sC[R * SCP + col + 1]       = acc[mi][ni][1];
            sC[(R + 8) * SCP + col]     = acc[mi][ni][2];
            sC[(R + 8) * SCP + col + 1] = acc[mi][ni][3];
        }
    }
    __syncthreads();

    // ---- bias + LayerNorm + relu + residual, one row per (warp, i) ----
    for (int i = 0; i < 8; i++) {
        int m = warp * 8 + i;
        float4 v = *(float4*)&sC[m * SCP + 4 * lane];
        float4 bi = __ldg(&((const float4*)bias_l)[lane]);
        v.x += bi.x; v.y += bi.y; v.z += bi.z; v.w += bi.w;
        float s = v.x + v.y + v.z + v.w;
#pragma unroll
        for (int o = 16; o; o >>= 1) s += __shfl_xor_sync(0xFFFFFFFFu, s, o);
        float mu = s * (1.0f / HH);
        float dx = v.x - mu, dy = v.y - mu, dz = v.z - mu, dw = v.w - mu;
        float q = dx * dx + dy * dy + dz * dz + dw * dw;
#pragma unroll
        for (int o = 16; o; o >>= 1) q += __shfl_xor_sync(0xFFFFFFFFu, q, o);
        float rs = rsqrtf(q * (1.0f / HH) + 1e-5f);
        float4 g4 = __ldg(&((const float4*)gam)[lane]);
        float4 b4 = __ldg(&((const float4*)bet)[lane]);
        float4 o4;
        o4.x = fmaxf(dx * rs * g4.x + b4.x, 0.f);
        o4.y = fmaxf(dy * rs * g4.y + b4.y, 0.f);
        o4.z = fmaxf(dz * rs * g4.z + b4.z, 0.f);
        o4.w = fmaxf(dw * rs * g4.w + b4.w, 0.f);
        if (residual) {
            float4 h4 = ((const float4*)(in + (size_t)(m0 + m) * HH))[lane];
            o4.x += h4.x; o4.y += h4.y; o4.z += h4.z; o4.w += h4.w;
        }
        ((float4*)(out + (size_t)(m0 + m) * HH))[lane] = o4;
    }
}

// ---------------- 3xTF32 GEMM (head): C = A1 @ B1 + bias, K=128 ----------------
#define KC   16
#define LDSA 136
__global__ void __launch_bounds__(256) k_gemm(
    const float* __restrict__ A1, int lda1, int k1,
    const float* __restrict__ B1,
    const float* __restrict__ bias, float* __restrict__ C, int relu)
{
    __shared__ float Ah[KC][LDSA], Al[KC][LDSA];
    __shared__ float Bh[KC][LDSA], Bl[KC][LDSA];

    int tid  = threadIdx.x;
    int warp = tid >> 5, lane = tid & 31;
    int wm = warp & 1, wn = warp >> 1;
    int g  = lane >> 2, t = lane & 3;
    int m0 = blockIdx.x * 128;

    float acc[4][4][4];
#pragma unroll
    for (int i = 0; i < 4; i++)
#pragma unroll
        for (int j = 0; j < 4; j++)
#pragma unroll
            for (int c = 0; c < 4; c++) acc[i][j][c] = 0.f;

    for (int kk = 0; kk < k1; kk += KC) {
        {
            int m   = tid >> 1;
            int kq0 = (tid & 1) * 8;
#pragma unroll
            for (int q = 0; q < 2; q++) {
                float4 v = *(const float4*)(A1 + (size_t)(m0 + m) * lda1 + kk + kq0 + q * 4);
                float e[4] = {v.x, v.y, v.z, v.w};
#pragma unroll
                for (int u = 0; u < 4; u++) {
                    float hi = tf32r(e[u]);
                    Ah[kq0 + q * 4 + u][m] = hi;
                    Al[kq0 + q * 4 + u][m] = tf32r(e[u] - hi);
                }
            }
        }
        {
            const float* Bp = B1 + (size_t)kk * HH;
            int kr  = tid >> 4;
            int cc0 = (tid & 15) * 8;
#pragma unroll
            for (int q = 0; q < 2; q++) {
                float4 v = *(const float4*)(Bp + (size_t)kr * HH + cc0 + q * 4);
                float e[4] = {v.x, v.y, v.z, v.w};
#pragma unroll
                for (int u = 0; u < 4; u++) {
                    float hi = tf32r(e[u]);
                    Bh[kr][cc0 + q * 4 + u] = hi;
                    Bl[kr][cc0 + q * 4 + u] = tf32r(e[u] - hi);
                }
            }
        }
        __syncthreads();

#pragma unroll
        for (int ks = 0; ks < KC / 8; ks++) {
            int k0 = ks * 8;
            uint32_t bh[4][2], bl[4][2];
#pragma unroll
            for (int ni = 0; ni < 4; ni++) {
                int nb = wn * 32 + ni * 8 + g;
                bh[ni][0] = __float_as_uint(Bh[k0 + t    ][nb]);
                bh[ni][1] = __float_as_uint(Bh[k0 + t + 4][nb]);
                bl[ni][0] = __float_as_uint(Bl[k0 + t    ][nb]);
                bl[ni][1] = __float_as_uint(Bl[k0 + t + 4][nb]);
            }
#pragma unroll
            for (int mi = 0; mi < 4; mi++) {
                int R = wm * 64 + mi * 16 + g;
                uint32_t ah0 = __float_as_uint(Ah[k0 + t    ][R]);
                uint32_t ah1 = __float_as_uint(Ah[k0 + t    ][R + 8]);
                uint32_t ah2 = __float_as_uint(Ah[k0 + t + 4][R]);
                uint32_t ah3 = __float_as_uint(Ah[k0 + t + 4][R + 8]);
                uint32_t al0 = __float_as_uint(Al[k0 + t    ][R]);
                uint32_t al1 = __float_as_uint(Al[k0 + t    ][R + 8]);
                uint32_t al2 = __float_as_uint(Al[k0 + t + 4][R]);
                uint32_t al3 = __float_as_uint(Al[k0 + t + 4][R + 8]);
#pragma unroll
                for (int ni = 0; ni < 4; ni++) {
                    float* c = acc[mi][ni];
                    mma_tf32(c[0], c[1], c[2], c[3], ah0, ah1, ah2, ah3, bh[ni][0], bh[ni][1]);
                    mma_tf32(c[0], c[1], c[2], c[3], ah0, ah1, ah2, ah3, bl[ni][0], bl[ni][1]);
                    mma_tf32(c[0], c[1], c[2], c[3], al0, al1, al2, al3, bh[ni][0], bh[ni][1]);
                }
            }
        }
        __syncthreads();
    }

#pragma unroll
    for (int ni = 0; ni < 4; ni++) {
        int col = wn * 32 + ni * 8 + 2 * t;
        float b0 = bias[col], b1 = bias[col + 1];
#pragma unroll
        for (int mi = 0; mi < 4; mi++) {
            int r0 = m0 + wm * 64 + mi * 16 + g;
            float* c = acc[mi][ni];
            float2 v0 = make_float2(c[0] + b0, c[1] + b1);
            float2 v1 = make_float2(c[2] + b0, c[3] + b1);
            if (relu) {
                v0.x = fmaxf(v0.x, 0.f); v0.y = fmaxf(v0.y, 0.f);
                v1.x = fmaxf(v1.x, 0.f); v1.y = fmaxf(v1.y, 0.f);
            }
            *(float2*)(C + (size_t)r0 * HH + col)       = v0;
            *(float2*)(C + (size_t)(r0 + 8) * HH + col) = v1;
        }
    }
}

// ---------------- head tail ----------------
__global__ void k_head2(const float* __restrict__ hid, const float* __restrict__ W2,
                        const float* __restrict__ b2, float* __restrict__ out) {
    int idx = blockIdx.x * blockDim.x + threadIdx.x;
    if (idx >= NN * OUTD) return;
    int n = idx >> 3, o = idx & 7;
    const float* hp = hid + (size_t)n * HH;
    float acc = b2[o];
#pragma unroll
    for (int k = 0; k < HH; k++) acc += hp[k] * W2[k * OUTD + o];
    out[idx] = acc;
}

// ---------------- launch ----------------
extern "C" void kernel_launch(void* const* d_in, const int* in_sizes, int n_in,
                              void* d_out, int out_size) {
    const float* x     = (const float*)d_in[0];
    const void*  ei    = d_in[1];
    const void*  et    = d_in[2];
    const float* W_in  = (const float*)d_in[3];
    const float* b_in  = (const float*)d_in[4];
    const float* basis = (const float*)d_in[5];
    const float* comp  = (const float*)d_in[6];
    const float* root  = (const float*)d_in[7];
    const float* bias  = (const float*)d_in[8];
    const float* ln_g  = (const float*)d_in[9];
    const float* ln_b  = (const float*)d_in[10];
    const float* W1    = (const float*)d_in[11];
    const float* b1    = (const float*)d_in[12];
    const float* W2    = (const float*)d_in[13];
    const float* b2    = (const float*)d_in[14];

    void *p_h, *p_t;
    cudaGetSymbolAddress(&p_h, g_h);
    cudaGetSymbolAddress(&p_t, g_t);
    cudaFuncSetAttribute(k_layer, cudaFuncAttributeMaxDynamicSharedMemorySize, SMEM_LAYER);

    // ---- one-time graph preprocessing ----
    k_detect<<<1, 256>>>((const int*)ei);
    k_prep<<<EE / 256, 256>>>(ei, et);
    k_zero_cnt<<<(NN * RR + 255) / 256, 256>>>();
    k_count<<<EE / 256, 256>>>();
    k_ps1<<<NN / 256, 256>>>();
    k_ps2<<<1, 512>>>();
    k_ps3<<<NN / 256, 256>>>();
    k_csr_scatter<<<EE / 256, 256>>>();
    k_inproj<<<NN / 8, 128>>>(x, W_in, b_in);

    // ---- fused layers (ping-pong g_h <-> g_t) ----
    float* bufs[2] = {(float*)p_h, (float*)p_t};
    for (int i = 0; i < LL; i++) {
        const float* in  = bufs[i & 1];
        float*       out = bufs[(i + 1) & 1];
        k_layer<<<NN / TM, 256, SMEM_LAYER>>>(
            in, out,
            comp + i * RR * BB,
            basis + (size_t)i * BB * HH * HH,
            root + (size_t)i * HH * HH,
            bias + i * HH, ln_g + i * HH, ln_b + i * HH, i > 0 ? 1 : 0);
    }
    // final h is in bufs[LL & 1] = g_t

    // ---- head: hidden = relu(h @ W1 + b1) -> g_h; out = hidden @ W2 + b2 ----
    k_gemm<<<NN / 128, 256>>>((const float*)p_t, HH, HH, W1, b1, (float*)p_h, 1);
    k_head2<<<NN * OUTD / 256, 256>>>((const float*)p_h, W2, b2, (float*)d_out);
}

// round 6
// speedup vs baseline: 3.1436x; 1.0718x over previous
#include <cuda_runtime.h>
#include <cuda_fp16.h>
#include <cstdint>

#define NN   131072
#define EE   2097152
#define FF   32
#define HH   128
#define RR   10
#define BB   4
#define LL   3
#define OUTD 8

#define TM   64               // fused-kernel block rows (dst nodes)
#define SAP  648              // sA k-stride in halves (640 + 8 pad)
#define SBP  26               // sB row stride in halves
#define SB_BUF (128 * SBP)    // halves per B buffer
#define SCP  132              // sC row stride in floats
#define SMEM_LAYER (TM * SAP * 2 + 2 * SB_BUF * 2)   // 96256 B

// ---------------- device scratch ----------------
__device__ float g_h  [(size_t)NN * HH];
__device__ float g_t  [(size_t)NN * HH];
__device__ float g_cnt[NN * RR];
__device__ int   g_src[EE];
__device__ int   g_dst[EE];
__device__ int   g_et [EE];
__device__ int   g_deg[NN];
__device__ int   g_row[NN + 1];
__device__ int   g_bsum[512];
__device__ int   g_cursor[NN];
__device__ int2  g_meta[EE];          // sorted {src|et<<20, bits(1/cnt)}
__device__ int   g_is64;

// ---------------- helpers ----------------
__device__ __forceinline__ float tf32r(float x) {
    uint32_t o;
    asm("cvt.rna.tf32.f32 %0, %1;" : "=r"(o) : "f"(x));
    return __uint_as_float(o);
}

__device__ __forceinline__ void mma_tf32(float& c0, float& c1, float& c2, float& c3,
                                         uint32_t a0, uint32_t a1, uint32_t a2, uint32_t a3,
                                         uint32_t b0, uint32_t b1) {
    asm volatile(
        "mma.sync.aligned.m16n8k8.row.col.f32.tf32.tf32.f32 "
        "{%0,%1,%2,%3}, {%4,%5,%6,%7}, {%8,%9}, {%0,%1,%2,%3};"
        : "+f"(c0), "+f"(c1), "+f"(c2), "+f"(c3)
        : "r"(a0), "r"(a1), "r"(a2), "r"(a3), "r"(b0), "r"(b1));
}

__device__ __forceinline__ void mma_f16(float* c,
                                        uint32_t a0, uint32_t a1, uint32_t a2, uint32_t a3,
                                        uint32_t b0, uint32_t b1) {
    asm volatile(
        "mma.sync.aligned.m16n8k16.row.col.f32.f16.f16.f32 "
        "{%0,%1,%2,%3}, {%4,%5,%6,%7}, {%8,%9}, {%0,%1,%2,%3};"
        : "+f"(c[0]), "+f"(c[1]), "+f"(c[2]), "+f"(c[3])
        : "r"(a0), "r"(a1), "r"(a2), "r"(a3), "r"(b0), "r"(b1));
}

// ---------------- dtype detect ----------------
__global__ void k_detect(const int* __restrict__ ei) {
    __shared__ int cnt;
    if (threadIdx.x == 0) cnt = 0;
    __syncthreads();
    if (ei[threadIdx.x * 2 + 1] != 0) atomicAdd(&cnt, 1);
    __syncthreads();
    if (threadIdx.x == 0) g_is64 = (cnt == 0) ? 1 : 0;
}

// ---------------- fused decode + degree/relation count ----------------
__global__ void k_prep_count(const void* __restrict__ ei_raw, const void* __restrict__ et_raw) {
    int e = blockIdx.x * blockDim.x + threadIdx.x;
    if (e >= EE) return;
    int s, d, t;
    if (g_is64) {
        const long long* ei = (const long long*)ei_raw;
        const long long* et = (const long long*)et_raw;
        s = (int)ei[e];
        d = (int)ei[(size_t)EE + e];
        t = (int)et[e];
    } else {
        const int* ei = (const int*)ei_raw;
        const int* et = (const int*)et_raw;
        s = ei[e];
        d = ei[EE + e];
        t = et[e];
    }
    g_src[e] = s;
    g_dst[e] = d;
    g_et[e]  = t;
    atomicAdd(&g_cnt[d * RR + t], 1.0f);
    atomicAdd(&g_deg[d], 1);
}

__global__ void k_zero_cnt() {
    int i = blockIdx.x * blockDim.x + threadIdx.x;
    if (i < NN * RR) g_cnt[i] = 0.0f;
    if (i < NN) g_deg[i] = 0;
}

// ---------------- prefix scan ----------------
__global__ void k_ps1() {
    __shared__ int sh[256];
    int i = blockIdx.x * 256 + threadIdx.x;
    int v = g_deg[i];
    sh[threadIdx.x] = v;
    __syncthreads();
#pragma unroll
    for (int o = 1; o < 256; o <<= 1) {
        int t = (threadIdx.x >= o) ? sh[threadIdx.x - o] : 0;
        __syncthreads();
        sh[threadIdx.x] += t;
        __syncthreads();
    }
    g_row[i] = sh[threadIdx.x] - v;
    if (threadIdx.x == 255) g_bsum[blockIdx.x] = sh[255];
}

__global__ void k_ps2() {
    __shared__ int sh[512];
    int v = g_bsum[threadIdx.x];
    sh[threadIdx.x] = v;
    __syncthreads();
#pragma unroll
    for (int o = 1; o < 512; o <<= 1) {
        int t = (threadIdx.x >= o) ? sh[threadIdx.x - o] : 0;
        __syncthreads();
        sh[threadIdx.x] += t;
        __syncthreads();
    }
    g_bsum[threadIdx.x] = sh[threadIdx.x] - v;
}

__global__ void k_ps3() {
    int i = blockIdx.x * 256 + threadIdx.x;
    int r = g_row[i] + g_bsum[i >> 8];
    g_row[i] = r;
    g_cursor[i] = r;
    if (i == 0) g_row[NN] = EE;
}

// ---------------- CSR scatter: interleaved packed metadata ----------------
__global__ void k_csr_scatter() {
    int e = blockIdx.x * blockDim.x + threadIdx.x;
    if (e >= EE) return;
    int d = g_dst[e];
    int t = g_et[e];
    int pos = atomicAdd(&g_cursor[d], 1);
    float inv = 1.0f / fmaxf(g_cnt[d * RR + t], 1.0f);
    g_meta[pos] = make_int2(g_src[e] | (t << 20), __float_as_int(inv));
}

// ---------------- input projection ----------------
__global__ void k_inproj(const float* __restrict__ x, const float* __restrict__ W,
                         const float* __restrict__ b) {
    __shared__ float Ws[FF * HH];
    __shared__ float xs[8][FF];
    int tid = threadIdx.x;
    for (int i = tid; i < FF * HH; i += 128) Ws[i] = W[i];
    int n0 = blockIdx.x * 8;
    for (int i = tid; i < 8 * FF; i += 128) xs[i / FF][i % FF] = x[(size_t)n0 * FF + i];
    __syncthreads();
    float bj = b[tid];
#pragma unroll
    for (int u = 0; u < 8; u++) {
        float acc = bj;
#pragma unroll
        for (int k = 0; k < FF; k++) acc += xs[u][k] * Ws[k * HH + tid];
        g_h[(size_t)(n0 + u) * HH + tid] = acc;
    }
}

// ================= fused RGCN layer =================
__global__ void __launch_bounds__(256, 2) k_layer(
    const float* __restrict__ in, float* __restrict__ out,
    const float* __restrict__ comp_l, const float* __restrict__ basis_l,
    const float* __restrict__ root_l, const float* __restrict__ bias_l,
    const float* __restrict__ gam, const float* __restrict__ bet, int residual)
{
    extern __shared__ __align__(16) char dyn[];
    __half* sA = (__half*)dyn;                       // [TM][SAP] k-cols
    __half* sB = (__half*)(dyn + TM * SAP * 2);      // 2 x [128][SBP]
    float*  sC = (float*)dyn;                        // epilogue reuse [TM][SCP]
    __shared__ float s_comp[RR * BB];

    int tid = threadIdx.x, warp = tid >> 5, lane = tid & 31;
    int m0 = blockIdx.x * TM;
    if (tid < RR * BB) s_comp[tid] = comp_l[tid];

    // ---- stage h (root-term planes 512..639) as fp16 ----
    for (int i = tid; i < TM * HH; i += 256) {
        int m = i >> 7, c = i & 127;
        sA[m * SAP + 512 + c] = __float2half_rn(in[(size_t)(m0 + m) * HH + c]);
    }
    __syncthreads();

    // ---- aggregation: 8 nodes per warp, 4-way unrolled gathers for MLP ----
#define ACC_EDGE(mt, vv)                                                     \
    {                                                                        \
        int   t_  = mt.x >> 20;                                              \
        float iv_ = __int_as_float(mt.y);                                    \
        float c0 = s_comp[t_ * BB + 0] * iv_;                                \
        float c1 = s_comp[t_ * BB + 1] * iv_;                                \
        float c2 = s_comp[t_ * BB + 2] * iv_;                                \
        float c3 = s_comp[t_ * BB + 3] * iv_;                                \
        a0.x += c0 * vv.x; a0.y += c0 * vv.y; a0.z += c0 * vv.z; a0.w += c0 * vv.w; \
        a1.x += c1 * vv.x; a1.y += c1 * vv.y; a1.z += c1 * vv.z; a1.w += c1 * vv.w; \
        a2.x += c2 * vv.x; a2.y += c2 * vv.y; a2.z += c2 * vv.z; a2.w += c2 * vv.w; \
        a3.x += c3 * vv.x; a3.y += c3 * vv.y; a3.z += c3 * vv.z; a3.w += c3 * vv.w; \
    }

    for (int ii = 0; ii < 8; ii++) {
        int m = warp * 8 + ii;
        int node = m0 + m;
        int beg = g_row[node], end = g_row[node + 1];
        float4 a0 = make_float4(0.f, 0.f, 0.f, 0.f);
        float4 a1 = a0, a2 = a0, a3 = a0;
        int e = beg;
        for (; e + 4 <= end; e += 4) {
            int2 m0_ = __ldg(&g_meta[e + 0]);
            int2 m1_ = __ldg(&g_meta[e + 1]);
            int2 m2_ = __ldg(&g_meta[e + 2]);
            int2 m3_ = __ldg(&g_meta[e + 3]);
            float4 v0 = __ldg(&((const float4*)(in + (size_t)(m0_.x & 0xFFFFF) * HH))[lane]);
            float4 v1 = __ldg(&((const float4*)(in + (size_t)(m1_.x & 0xFFFFF) * HH))[lane]);
            float4 v2 = __ldg(&((const float4*)(in + (size_t)(m2_.x & 0xFFFFF) * HH))[lane]);
            float4 v3 = __ldg(&((const float4*)(in + (size_t)(m3_.x & 0xFFFFF) * HH))[lane]);
            ACC_EDGE(m0_, v0);
            ACC_EDGE(m1_, v1);
            ACC_EDGE(m2_, v2);
            ACC_EDGE(m3_, v3);
        }
        for (; e < end; e++) {
            int2 mt = __ldg(&g_meta[e]);
            float4 vv = __ldg(&((const float4*)(in + (size_t)(mt.x & 0xFFFFF) * HH))[lane]);
            ACC_EDGE(mt, vv);
        }
        __half* dst = sA + m * SAP + 4 * lane;
        *(__half2*)(dst + 0 * 128 + 0) = __floats2half2_rn(a0.x, a0.y);
        *(__half2*)(dst + 0 * 128 + 2) = __floats2half2_rn(a0.z, a0.w);
        *(__half2*)(dst + 1 * 128 + 0) = __floats2half2_rn(a1.x, a1.y);
        *(__half2*)(dst + 1 * 128 + 2) = __floats2half2_rn(a1.z, a1.w);
        *(__half2*)(dst + 2 * 128 + 0) = __floats2half2_rn(a2.x, a2.y);
        *(__half2*)(dst + 2 * 128 + 2) = __floats2half2_rn(a2.z, a2.w);
        *(__half2*)(dst + 3 * 128 + 0) = __floats2half2_rn(a3.x, a3.y);
        *(__half2*)(dst + 3 * 128 + 2) = __floats2half2_rn(a3.z, a3.w);
    }
#undef ACC_EDGE
    __syncthreads();

    // ---- GEMM: [TM x 640] @ [640 x 128], fp16 mma, 2m x 4n warp grid ----
    int wm = warp & 1, wn = warp >> 1;
    int g = lane >> 2, t = lane & 3;
    float acc[2][4][4];
#pragma unroll
    for (int i = 0; i < 2; i++)
#pragma unroll
        for (int j = 0; j < 4; j++)
#pragma unroll
            for (int c = 0; c < 4; c++) acc[i][j][c] = 0.f;

    int kr  = tid >> 4;              // 0..15
    int c0b = (tid & 15) * 8;        // 0..120
    float4 pb0, pb1;

    {
        const float* bp = basis_l + (size_t)kr * HH;
        pb0 = *(const float4*)(bp + c0b);
        pb1 = *(const float4*)(bp + c0b + 4);
        __half* d = sB + 0;
        d[(c0b + 0) * SBP + kr] = __float2half_rn(pb0.x);
        d[(c0b + 1) * SBP + kr] = __float2half_rn(pb0.y);
        d[(c0b + 2) * SBP + kr] = __float2half_rn(pb0.z);
        d[(c0b + 3) * SBP + kr] = __float2half_rn(pb0.w);
        d[(c0b + 4) * SBP + kr] = __float2half_rn(pb1.x);
        d[(c0b + 5) * SBP + kr] = __float2half_rn(pb1.y);
        d[(c0b + 6) * SBP + kr] = __float2half_rn(pb1.z);
        d[(c0b + 7) * SBP + kr] = __float2half_rn(pb1.w);
    }
    __syncthreads();

    for (int kc = 0; kc < 40; kc++) {
        if (kc < 39) {
            int kg = (kc + 1) * 16 + kr;
            const float* bp = (kg < 512) ? basis_l + (size_t)kg * HH
                                         : root_l + (size_t)(kg - 512) * HH;
            pb0 = *(const float4*)(bp + c0b);
            pb1 = *(const float4*)(bp + c0b + 4);
        }
        const __half* bb = sB + (kc & 1) * SB_BUF;
        int ka = kc * 16 + 2 * t;
        uint32_t Bf[4][2];
#pragma unroll
        for (int ni = 0; ni < 4; ni++) {
            int n = wn * 32 + ni * 8 + g;
            Bf[ni][0] = *(const uint32_t*)&bb[n * SBP + 2 * t];
            Bf[ni][1] = *(const uint32_t*)&bb[n * SBP + 2 * t + 8];
        }
#pragma unroll
        for (int mi = 0; mi < 2; mi++) {
            int R = wm * 32 + mi * 16 + g;
            uint32_t A0 = *(const uint32_t*)&sA[R * SAP + ka];
            uint32_t A1 = *(const uint32_t*)&sA[(R + 8) * SAP + ka];
            uint32_t A2 = *(const uint32_t*)&sA[R * SAP + ka + 8];
            uint32_t A3 = *(const uint32_t*)&sA[(R + 8) * SAP + ka + 8];
#pragma unroll
            for (int ni = 0; ni < 4; ni++)
                mma_f16(acc[mi][ni], A0, A1, A2, A3, Bf[ni][0], Bf[ni][1]);
        }
        if (kc < 39) {
            __half* d = sB + ((kc + 1) & 1) * SB_BUF;
            d[(c0b + 0) * SBP + kr] = __float2half_rn(pb0.x);
            d[(c0b + 1) * SBP + kr] = __float2half_rn(pb0.y);
            d[(c0b + 2) * SBP + kr] = __float2half_rn(pb0.z);
            d[(c0b + 3) * SBP + kr] = __float2half_rn(pb0.w);
            d[(c0b + 4) * SBP + kr] = __float2half_rn(pb1.x);
            d[(c0b + 5) * SBP + kr] = __float2half_rn(pb1.y);
            d[(c0b + 6) * SBP + kr] = __float2half_rn(pb1.z);
            d[(c0b + 7) * SBP + kr] = __float2half_rn(pb1.w);
        }
        __syncthreads();
    }

    // ---- epilogue: stage C to smem ----
#pragma unroll
    for (int mi = 0; mi < 2; mi++) {
        int R = wm * 32 + mi * 16 + g;
#pragma unroll
        for (int ni = 0; ni < 4; ni++) {
            int col = wn * 32 + ni * 8 + 2 * t;
            sC[R * SCP + col]           = acc[mi][ni][0];
            sC[R * SCP + col + 1]       = acc[mi][ni][1];
            sC[(R + 8) * SCP + col]     = acc[mi][ni][2];
            sC[(R + 8) * SCP + col + 1] = acc[mi][ni][3];
        }
    }
    __syncthreads();

    // ---- bias + LayerNorm + relu + residual ----
    for (int i = 0; i < 8; i++) {
        int m = warp * 8 + i;
        float4 v = *(float4*)&sC[m * SCP + 4 * lane];
        float4 bi = __ldg(&((const float4*)bias_l)[lane]);
        v.x += bi.x; v.y += bi.y; v.z += bi.z; v.w += bi.w;
        float s = v.x + v.y + v.z + v.w;
#pragma unroll
        for (int o = 16; o; o >>= 1) s += __shfl_xor_sync(0xFFFFFFFFu, s, o);
        float mu = s * (1.0f / HH);
        float dx = v.x - mu, dy = v.y - mu, dz = v.z - mu, dw = v.w - mu;
        float q = dx * dx + dy * dy + dz * dz + dw * dw;
#pragma unroll
        for (int o = 16; o; o >>= 1) q += __shfl_xor_sync(0xFFFFFFFFu, q, o);
        float rs = rsqrtf(q * (1.0f / HH) + 1e-5f);
        float4 g4 = __ldg(&((const float4*)gam)[lane]);
        float4 b4 = __ldg(&((const float4*)bet)[lane]);
        float4 o4;
        o4.x = fmaxf(dx * rs * g4.x + b4.x, 0.f);
        o4.y = fmaxf(dy * rs * g4.y + b4.y, 0.f);
        o4.z = fmaxf(dz * rs * g4.z + b4.z, 0.f);
        o4.w = fmaxf(dw * rs * g4.w + b4.w, 0.f);
        if (residual) {
            float4 h4 = ((const float4*)(in + (size_t)(m0 + m) * HH))[lane];
            o4.x += h4.x; o4.y += h4.y; o4.z += h4.z; o4.w += h4.w;
        }
        ((float4*)(out + (size_t)(m0 + m) * HH))[lane] = o4;
    }
}

// ---------------- 3xTF32 GEMM (head): C = A1 @ B1 + bias, K=128 ----------------
#define KC   16
#define LDSA 136
__global__ void __launch_bounds__(256) k_gemm(
    const float* __restrict__ A1, int lda1, int k1,
    const float* __restrict__ B1,
    const float* __restrict__ bias, float* __restrict__ C, int relu)
{
    __shared__ float Ah[KC][LDSA], Al[KC][LDSA];
    __shared__ float Bh[KC][LDSA], Bl[KC][LDSA];

    int tid  = threadIdx.x;
    int warp = tid >> 5, lane = tid & 31;
    int wm = warp & 1, wn = warp >> 1;
    int g  = lane >> 2, t = lane & 3;
    int m0 = blockIdx.x * 128;

    float acc[4][4][4];
#pragma unroll
    for (int i = 0; i < 4; i++)
#pragma unroll
        for (int j = 0; j < 4; j++)
#pragma unroll
            for (int c = 0; c < 4; c++) acc[i][j][c] = 0.f;

    for (int kk = 0; kk < k1; kk += KC) {
        {
            int m   = tid >> 1;
            int kq0 = (tid & 1) * 8;
#pragma unroll
            for (int q = 0; q < 2; q++) {
                float4 v = *(const float4*)(A1 + (size_t)(m0 + m) * lda1 + kk + kq0 + q * 4);
                float e[4] = {v.x, v.y, v.z, v.w};
#pragma unroll
                for (int u = 0; u < 4; u++) {
                    float hi = tf32r(e[u]);
                    Ah[kq0 + q * 4 + u][m] = hi;
                    Al[kq0 + q * 4 + u][m] = tf32r(e[u] - hi);
                }
            }
        }
        {
            const float* Bp = B1 + (size_t)kk * HH;
            int kr  = tid >> 4;
            int cc0 = (tid & 15) * 8;
#pragma unroll
            for (int q = 0; q < 2; q++) {
                float4 v = *(const float4*)(Bp + (size_t)kr * HH + cc0 + q * 4);
                float e[4] = {v.x, v.y, v.z, v.w};
#pragma unroll
                for (int u = 0; u < 4; u++) {
                    float hi = tf32r(e[u]);
                    Bh[kr][cc0 + q * 4 + u] = hi;
                    Bl[kr][cc0 + q * 4 + u] = tf32r(e[u] - hi);
                }
            }
        }
        __syncthreads();

#pragma unroll
        for (int ks = 0; ks < KC / 8; ks++) {
            int k0 = ks * 8;
            uint32_t bh[4][2], bl[4][2];
#pragma unroll
            for (int ni = 0; ni < 4; ni++) {
                int nb = wn * 32 + ni * 8 + g;
                bh[ni][0] = __float_as_uint(Bh[k0 + t    ][nb]);
                bh[ni][1] = __float_as_uint(Bh[k0 + t + 4][nb]);
                bl[ni][0] = __float_as_uint(Bl[k0 + t    ][nb]);
                bl[ni][1] = __float_as_uint(Bl[k0 + t + 4][nb]);
            }
#pragma unroll
            for (int mi = 0; mi < 4; mi++) {
                int R = wm * 64 + mi * 16 + g;
                uint32_t ah0 = __float_as_uint(Ah[k0 + t    ][R]);
                uint32_t ah1 = __float_as_uint(Ah[k0 + t    ][R + 8]);
                uint32_t ah2 = __float_as_uint(Ah[k0 + t + 4][R]);
                uint32_t ah3 = __float_as_uint(Ah[k0 + t + 4][R + 8]);
                uint32_t al0 = __float_as_uint(Al[k0 + t    ][R]);
                uint32_t al1 = __float_as_uint(Al[k0 + t    ][R + 8]);
                uint32_t al2 = __float_as_uint(Al[k0 + t + 4][R]);
                uint32_t al3 = __float_as_uint(Al[k0 + t + 4][R + 8]);
#pragma unroll
                for (int ni = 0; ni < 4; ni++) {
                    float* c = acc[mi][ni];
                    mma_tf32(c[0], c[1], c[2], c[3], ah0, ah1, ah2, ah3, bh[ni][0], bh[ni][1]);
                    mma_tf32(c[0], c[1], c[2], c[3], ah0, ah1, ah2, ah3, bl[ni][0], bl[ni][1]);
                    mma_tf32(c[0], c[1], c[2], c[3], al0, al1, al2, al3, bh[ni][0], bh[ni][1]);
                }
            }
        }
        __syncthreads();
    }

#pragma unroll
    for (int ni = 0; ni < 4; ni++) {
        int col = wn * 32 + ni * 8 + 2 * t;
        float b0 = bias[col], b1 = bias[col + 1];
#pragma unroll
        for (int mi = 0; mi < 4; mi++) {
            int r0 = m0 + wm * 64 + mi * 16 + g;
            float* c = acc[mi][ni];
            float2 v0 = make_float2(c[0] + b0, c[1] + b1);
            float2 v1 = make_float2(c[2] + b0, c[3] + b1);
            if (relu) {
                v0.x = fmaxf(v0.x, 0.f); v0.y = fmaxf(v0.y, 0.f);
                v1.x = fmaxf(v1.x, 0.f); v1.y = fmaxf(v1.y, 0.f);
            }
            *(float2*)(C + (size_t)r0 * HH + col)       = v0;
            *(float2*)(C + (size_t)(r0 + 8) * HH + col) = v1;
        }
    }
}

// ---------------- head tail ----------------
__global__ void k_head2(const float* __restrict__ hid, const float* __restrict__ W2,
                        const float* __restrict__ b2, float* __restrict__ out) {
    int idx = blockIdx.x * blockDim.x + threadIdx.x;
    if (idx >= NN * OUTD) return;
    int n = idx >> 3, o = idx & 7;
    const float* hp = hid + (size_t)n * HH;
    float acc = b2[o];
#pragma unroll
    for (int k = 0; k < HH; k++) acc += hp[k] * W2[k * OUTD + o];
    out[idx] = acc;
}

// ---------------- launch ----------------
extern "C" void kernel_launch(void* const* d_in, const int* in_sizes, int n_in,
                              void* d_out, int out_size) {
    const float* x     = (const float*)d_in[0];
    const void*  ei    = d_in[1];
    const void*  et    = d_in[2];
    const float* W_in  = (const float*)d_in[3];
    const float* b_in  = (const float*)d_in[4];
    const float* basis = (const float*)d_in[5];
    const float* comp  = (const float*)d_in[6];
    const float* root  = (const float*)d_in[7];
    const float* bias  = (const float*)d_in[8];
    const float* ln_g  = (const float*)d_in[9];
    const float* ln_b  = (const float*)d_in[10];
    const float* W1    = (const float*)d_in[11];
    const float* b1    = (const float*)d_in[12];
    const float* W2    = (const float*)d_in[13];
    const float* b2    = (const float*)d_in[14];

    void *p_h, *p_t;
    cudaGetSymbolAddress(&p_h, g_h);
    cudaGetSymbolAddress(&p_t, g_t);
    cudaFuncSetAttribute(k_layer, cudaFuncAttributeMaxDynamicSharedMemorySize, SMEM_LAYER);

    // ---- one-time graph preprocessing ----
    k_detect<<<1, 256>>>((const int*)ei);
    k_zero_cnt<<<(NN * RR + 255) / 256, 256>>>();
    k_prep_count<<<EE / 256, 256>>>(ei, et);
    k_ps1<<<NN / 256, 256>>>();
    k_ps2<<<1, 512>>>();
    k_ps3<<<NN / 256, 256>>>();
    k_csr_scatter<<<EE / 256, 256>>>();
    k_inproj<<<NN / 8, 128>>>(x, W_in, b_in);

    // ---- fused layers (ping-pong g_h <-> g_t) ----
    float* bufs[2] = {(float*)p_h, (float*)p_t};
    for (int i = 0; i < LL; i++) {
        const float* in  = bufs[i & 1];
        float*       out = bufs[(i + 1) & 1];
        k_layer<<<NN / TM, 256, SMEM_LAYER>>>(
            in, out,
            comp + i * RR * BB,
            basis + (size_t)i * BB * HH * HH,
            root + (size_t)i * HH * HH,
            bias + i * HH, ln_g + i * HH, ln_b + i * HH, i > 0 ? 1 : 0);
    }

    // ---- head: hidden = relu(h @ W1 + b1) -> g_h; out = hidden @ W2 + b2 ----
    k_gemm<<<NN / 128, 256>>>((const float*)p_t, HH, HH, W1, b1, (float*)p_h, 1);
    k_head2<<<NN * OUTD / 256, 256>>>((const float*)p_h, W2, b2, (float*)d_out);
}

// round 8
// speedup vs baseline: 4.4177x; 1.4053x over previous
#include <cuda_runtime.h>
#include <cuda_fp16.h>
#include <cstdint>

#define NN   131072
#define EE   2097152
#define FF   32
#define HH   128
#define RR   10
#define BB   4
#define LL   3
#define OUTD 8

#define TM   64               // fused-kernel block rows (dst nodes)
#define SAP  648              // sA k-stride in halves (640 + 8 pad)
#define SBP  24               // sB row stride in halves (16 used + 8 pad; word stride 12)
#define SB_BUF (128 * SBP)    // halves per B buffer
#define SCP  132              // sC row stride in floats
#define NCH  40               // K chunks of 16 (640 total)
#define SMEM_LAYER (TM * SAP * 2 + 2 * SB_BUF * 2)   // 82944 + 12288 = 95232 B
#define SMEM_HEAD  (TM * 2 * SCP * 4)                // 128*132 floats = 67584 B

// ---------------- device scratch ----------------
__device__ float  g_h  [(size_t)NN * HH];
__device__ float  g_t  [(size_t)NN * HH];
__device__ __half g_hh0[(size_t)NN * HH];   // fp16 mirror (ping)
__device__ __half g_hh1[(size_t)NN * HH];   // fp16 mirror (pong)
__device__ __half g_wB [(size_t)LL * NCH * 128 * 16]; // staged fp16 weights
__device__ float  g_cnt[NN * RR];
__device__ int    g_src[EE];
__device__ int    g_dst[EE];
__device__ int    g_et [EE];
__device__ int    g_deg[NN];
__device__ int    g_row[NN + 1];
__device__ int    g_bsum[512];
__device__ int    g_cursor[NN];
__device__ int2   g_meta[EE];          // sorted {src|et<<20, bits(1/cnt)}
__device__ int    g_is64;

// ---------------- helpers ----------------
__device__ __forceinline__ float tf32r(float x) {
    uint32_t o;
    asm("cvt.rna.tf32.f32 %0, %1;" : "=r"(o) : "f"(x));
    return __uint_as_float(o);
}

__device__ __forceinline__ void mma_tf32(float& c0, float& c1, float& c2, float& c3,
                                         uint32_t a0, uint32_t a1, uint32_t a2, uint32_t a3,
                                         uint32_t b0, uint32_t b1) {
    asm volatile(
        "mma.sync.aligned.m16n8k8.row.col.f32.tf32.tf32.f32 "
        "{%0,%1,%2,%3}, {%4,%5,%6,%7}, {%8,%9}, {%0,%1,%2,%3};"
        : "+f"(c0), "+f"(c1), "+f"(c2), "+f"(c3)
        : "r"(a0), "r"(a1), "r"(a2), "r"(a3), "r"(b0), "r"(b1));
}

__device__ __forceinline__ void mma_f16(float* c,
                                        uint32_t a0, uint32_t a1, uint32_t a2, uint32_t a3,
                                        uint32_t b0, uint32_t b1) {
    asm volatile(
        "mma.sync.aligned.m16n8k16.row.col.f32.f16.f16.f32 "
        "{%0,%1,%2,%3}, {%4,%5,%6,%7}, {%8,%9}, {%0,%1,%2,%3};"
        : "+f"(c[0]), "+f"(c[1]), "+f"(c[2]), "+f"(c[3])
        : "r"(a0), "r"(a1), "r"(a2), "r"(a3), "r"(b0), "r"(b1));
}

// ---------------- dtype detect ----------------
__global__ void k_detect(const int* __restrict__ ei) {
    __shared__ int cnt;
    if (threadIdx.x == 0) cnt = 0;
    __syncthreads();
    if (ei[threadIdx.x * 2 + 1] != 0) atomicAdd(&cnt, 1);
    __syncthreads();
    if (threadIdx.x == 0) g_is64 = (cnt == 0) ? 1 : 0;
}

// ---------------- fused decode + degree/relation count ----------------
__global__ void k_prep_count(const void* __restrict__ ei_raw, const void* __restrict__ et_raw) {
    int e = blockIdx.x * blockDim.x + threadIdx.x;
    if (e >= EE) return;
    int s, d, t;
    if (g_is64) {
        const long long* ei = (const long long*)ei_raw;
        const long long* et = (const long long*)et_raw;
        s = (int)ei[e];
        d = (int)ei[(size_t)EE + e];
        t = (int)et[e];
    } else {
        const int* ei = (const int*)ei_raw;
        const int* et = (const int*)et_raw;
        s = ei[e];
        d = ei[EE + e];
        t = et[e];
    }
    g_src[e] = s;
    g_dst[e] = d;
    g_et[e]  = t;
    atomicAdd(&g_cnt[d * RR + t], 1.0f);
    atomicAdd(&g_deg[d], 1);
}

__global__ void k_zero_cnt() {
    int i = blockIdx.x * blockDim.x + threadIdx.x;
    if (i < NN * RR) g_cnt[i] = 0.0f;
    if (i < NN) g_deg[i] = 0;
}

// ---------------- prefix scan ----------------
__global__ void k_ps1() {
    __shared__ int sh[256];
    int i = blockIdx.x * 256 + threadIdx.x;
    int v = g_deg[i];
    sh[threadIdx.x] = v;
    __syncthreads();
#pragma unroll
    for (int o = 1; o < 256; o <<= 1) {
        int t = (threadIdx.x >= o) ? sh[threadIdx.x - o] : 0;
        __syncthreads();
        sh[threadIdx.x] += t;
        __syncthreads();
    }
    g_row[i] = sh[threadIdx.x] - v;
    if (threadIdx.x == 255) g_bsum[blockIdx.x] = sh[255];
}

__global__ void k_ps2() {
    __shared__ int sh[512];
    int v = g_bsum[threadIdx.x];
    sh[threadIdx.x] = v;
    __syncthreads();
#pragma unroll
    for (int o = 1; o < 512; o <<= 1) {
        int t = (threadIdx.x >= o) ? sh[threadIdx.x - o] : 0;
        __syncthreads();
        sh[threadIdx.x] += t;
        __syncthreads();
    }
    g_bsum[threadIdx.x] = sh[threadIdx.x] - v;
}

__global__ void k_ps3() {
    int i = blockIdx.x * 256 + threadIdx.x;
    int r = g_row[i] + g_bsum[i >> 8];
    g_row[i] = r;
    g_cursor[i] = r;
    if (i == 0) g_row[NN] = EE;
}

// ---------------- CSR scatter: interleaved packed metadata ----------------
__global__ void k_csr_scatter() {
    int e = blockIdx.x * blockDim.x + threadIdx.x;
    if (e >= EE) return;
    int d = g_dst[e];
    int t = g_et[e];
    int pos = atomicAdd(&g_cursor[d], 1);
    float inv = 1.0f / fmaxf(g_cnt[d * RR + t], 1.0f);
    g_meta[pos] = make_int2(g_src[e] | (t << 20), __float_as_int(inv));
}

// ---------------- weight preconvert: basis||root -> staged fp16 [NCH][128][16] ----------------
__global__ void k_wconv(const float* __restrict__ basis, const float* __restrict__ root) {
    int idx = blockIdx.x * blockDim.x + threadIdx.x;   // over LL*NCH*128*16
    if (idx >= LL * NCH * 128 * 16) return;
    int l   = idx / (NCH * 128 * 16);
    int rem = idx % (NCH * 128 * 16);
    int kc  = rem >> 11;
    int n   = (rem >> 4) & 127;
    int kr  = rem & 15;
    int kg  = kc * 16 + kr;
    float v = (kg < 512) ? basis[(size_t)l * 512 * HH + (size_t)kg * HH + n]
                         : root [(size_t)l * HH * HH + (size_t)(kg - 512) * HH + n];
    g_wB[idx] = __float2half_rn(v);
}

// ---------------- input projection (writes fp32 + fp16 mirror) ----------------
__global__ void k_inproj(const float* __restrict__ x, const float* __restrict__ W,
                         const float* __restrict__ b) {
    __shared__ float Ws[FF * HH];
    __shared__ float xs[8][FF];
    int tid = threadIdx.x;
    for (int i = tid; i < FF * HH; i += 128) Ws[i] = W[i];
    int n0 = blockIdx.x * 8;
    for (int i = tid; i < 8 * FF; i += 128) xs[i / FF][i % FF] = x[(size_t)n0 * FF + i];
    __syncthreads();
    float bj = b[tid];
#pragma unroll
    for (int u = 0; u < 8; u++) {
        float acc = bj;
#pragma unroll
        for (int k = 0; k < FF; k++) acc += xs[u][k] * Ws[k * HH + tid];
        g_h  [(size_t)(n0 + u) * HH + tid] = acc;
        g_hh0[(size_t)(n0 + u) * HH + tid] = __float2half_rn(acc);
    }
}

// ================= fused RGCN layer =================
__global__ void __launch_bounds__(256, 2) k_layer(
    const float* __restrict__ in, float* __restrict__ out,
    const __half* __restrict__ hh_in, __half* __restrict__ hh_out,
    const __half* __restrict__ wB_l,
    const float* __restrict__ comp_l, const float* __restrict__ bias_l,
    const float* __restrict__ gam, const float* __restrict__ bet, int residual)
{
    extern __shared__ __align__(16) char dyn[];
    __half* sA = (__half*)dyn;                       // [TM][SAP] k-cols
    __half* sB = (__half*)(dyn + TM * SAP * 2);      // 2 x [128][SBP]
    float*  sC = (float*)dyn;                        // epilogue reuse [TM][SCP]
    __shared__ float s_comp[RR * BB];

    int tid = threadIdx.x, warp = tid >> 5, lane = tid & 31;
    int m0 = blockIdx.x * TM;
    if (tid < RR * BB) s_comp[tid] = comp_l[tid];

    // ---- stage h (root planes 512..639) straight from fp16 mirror ----
    for (int i = tid; i < TM * HH / 8; i += 256) {
        int m = i >> 4, c8 = i & 15;
        *(uint4*)(sA + m * SAP + 512 + c8 * 8) =
            ((const uint4*)(hh_in + (size_t)(m0 + m) * HH))[c8];
    }
    __syncthreads();

    // ---- aggregation: 8 nodes per warp, fp16 gathers (8B/lane), 4-way unrolled ----
#define ACC_EDGE(mt, r)                                                       \
    {                                                                         \
        int   t_  = mt.x >> 20;                                               \
        float iv_ = __int_as_float(mt.y);                                     \
        float c0 = s_comp[t_ * BB + 0] * iv_;                                 \
        float c1 = s_comp[t_ * BB + 1] * iv_;                                 \
        float c2 = s_comp[t_ * BB + 2] * iv_;                                 \
        float c3 = s_comp[t_ * BB + 3] * iv_;                                 \
        float2 p0 = __half22float2(*(__half2*)&r.x);                          \
        float2 p1 = __half22float2(*(__half2*)&r.y);                          \
        a0.x += c0 * p0.x; a0.y += c0 * p0.y; a0.z += c0 * p1.x; a0.w += c0 * p1.y; \
        a1.x += c1 * p0.x; a1.y += c1 * p0.y; a1.z += c1 * p1.x; a1.w += c1 * p1.y; \
        a2.x += c2 * p0.x; a2.y += c2 * p0.y; a2.z += c2 * p1.x; a2.w += c2 * p1.y; \
        a3.x += c3 * p0.x; a3.y += c3 * p0.y; a3.z += c3 * p1.x; a3.w += c3 * p1.y; \
    }

    for (int ii = 0; ii < 8; ii++) {
        int m = warp * 8 + ii;
        int node = m0 + m;
        int beg = g_row[node], end = g_row[node + 1];
        float4 a0 = make_float4(0.f, 0.f, 0.f, 0.f);
        float4 a1 = a0, a2 = a0, a3 = a0;
        int e = beg;
        for (; e + 4 <= end; e += 4) {
            int2 m0_ = __ldg(&g_meta[e + 0]);
            int2 m1_ = __ldg(&g_meta[e + 1]);
            int2 m2_ = __ldg(&g_meta[e + 2]);
            int2 m3_ = __ldg(&g_meta[e + 3]);
            uint2 r0 = __ldg((const uint2*)(hh_in + (size_t)(m0_.x & 0xFFFFF) * HH) + lane);
            uint2 r1 = __ldg((const uint2*)(hh_in + (size_t)(m1_.x & 0xFFFFF) * HH) + lane);
            uint2 r2 = __ldg((const uint2*)(hh_in + (size_t)(m2_.x & 0xFFFFF) * HH) + lane);
            uint2 r3 = __ldg((const uint2*)(hh_in + (size_t)(m3_.x & 0xFFFFF) * HH) + lane);
            ACC_EDGE(m0_, r0);
            ACC_EDGE(m1_, r1);
            ACC_EDGE(m2_, r2);
            ACC_EDGE(m3_, r3);
        }
        for (; e < end; e++) {
            int2 mt = __ldg(&g_meta[e]);
            uint2 rr = __ldg((const uint2*)(hh_in + (size_t)(mt.x & 0xFFFFF) * HH) + lane);
            ACC_EDGE(mt, rr);
        }
        __half* dst = sA + m * SAP + 4 * lane;
        *(__half2*)(dst + 0 * 128 + 0) = __floats2half2_rn(a0.x, a0.y);
        *(__half2*)(dst + 0 * 128 + 2) = __floats2half2_rn(a0.z, a0.w);
        *(__half2*)(dst + 1 * 128 + 0) = __floats2half2_rn(a1.x, a1.y);
        *(__half2*)(dst + 1 * 128 + 2) = __floats2half2_rn(a1.z, a1.w);
        *(__half2*)(dst + 2 * 128 + 0) = __floats2half2_rn(a2.x, a2.y);
        *(__half2*)(dst + 2 * 128 + 2) = __floats2half2_rn(a2.z, a2.w);
        *(__half2*)(dst + 3 * 128 + 0) = __floats2half2_rn(a3.x, a3.y);
        *(__half2*)(dst + 3 * 128 + 2) = __floats2half2_rn(a3.z, a3.w);
    }
#undef ACC_EDGE
    __syncthreads();

    // ---- GEMM: [TM x 640] @ [640 x 128], fp16 mma, 2m x 4n warp grid ----
    int wm = warp & 1, wn = warp >> 1;
    int g = lane >> 2, t = lane & 3;
    float acc[2][4][4];
#pragma unroll
    for (int i = 0; i < 2; i++)
#pragma unroll
        for (int j = 0; j < 4; j++)
#pragma unroll
            for (int c = 0; c < 4; c++) acc[i][j][c] = 0.f;

    int nB = tid >> 1;               // 0..127
    int hp = tid & 1;                // uint4 half-row part
    uint4 pb;

    // prologue: stage chunk 0
    pb = ((const uint4*)wB_l)[(size_t)(0 * 128 + nB) * 2 + hp];
    *(uint4*)(sB + nB * SBP + hp * 8) = pb;
    __syncthreads();

    for (int kc = 0; kc < NCH; kc++) {
        if (kc < NCH - 1)
            pb = ((const uint4*)wB_l)[(size_t)((kc + 1) * 128 + nB) * 2 + hp];
        const __half* bb = sB + (kc & 1) * SB_BUF;
        int ka = kc * 16 + 2 * t;
        uint32_t Bf[4][2];
#pragma unroll
        for (int ni = 0; ni < 4; ni++) {
            int n = wn * 32 + ni * 8 + g;
            Bf[ni][0] = *(const uint32_t*)&bb[n * SBP + 2 * t];
            Bf[ni][1] = *(const uint32_t*)&bb[n * SBP + 2 * t + 8];
        }
#pragma unroll
        for (int mi = 0; mi < 2; mi++) {
            int R = wm * 32 + mi * 16 + g;
            uint32_t A0 = *(const uint32_t*)&sA[R * SAP + ka];
            uint32_t A1 = *(const uint32_t*)&sA[(R + 8) * SAP + ka];
            uint32_t A2 = *(const uint32_t*)&sA[R * SAP + ka + 8];
            uint32_t A3 = *(const uint32_t*)&sA[(R + 8) * SAP + ka + 8];
#pragma unroll
            for (int ni = 0; ni < 4; ni++)
                mma_f16(acc[mi][ni], A0, A1, A2, A3, Bf[ni][0], Bf[ni][1]);
        }
        if (kc < NCH - 1)
            *(uint4*)(sB + ((kc + 1) & 1) * SB_BUF + nB * SBP + hp * 8) = pb;
        __syncthreads();
    }

    // ---- epilogue: stage C to smem (sA no longer needed) ----
#pragma unroll
    for (int mi = 0; mi < 2; mi++) {
        int R = wm * 32 + mi * 16 + g;
#pragma unroll
        for (int ni = 0; ni < 4; ni++) {
            int col = wn * 32 + ni * 8 + 2 * t;
            sC[R * SCP + col]           = acc[mi][ni][0];
            sC[R * SCP + col + 1]       = acc[mi][ni][1];
            sC[(R + 8) * SCP + col]     = acc[mi][ni][2];
            sC[(R + 8) * SCP + col + 1] = acc[mi][ni][3];
        }
    }
    __syncthreads();

    // ---- bias + LayerNorm + relu + residual; write fp32 + fp16 mirror ----
    for (int i = 0; i < 8; i++) {
        int m = warp * 8 + i;
        float4 v = *(float4*)&sC[m * SCP + 4 * lane];
        float4 bi = __ldg(&((const float4*)bias_l)[lane]);
        v.x += bi.x; v.y += bi.y; v.z += bi.z; v.w += bi.w;
        float s = v.x + v.y + v.z + v.w;
#pragma unroll
        for (int o = 16; o; o >>= 1) s += __shfl_xor_sync(0xFFFFFFFFu, s, o);
        float mu = s * (1.0f / HH);
        float dx = v.x - mu, dy = v.y - mu, dz = v.z - mu, dw = v.w - mu;
        float q = dx * dx + dy * dy + dz * dz + dw * dw;
#pragma unroll
        for (int o = 16; o; o >>= 1) q += __shfl_xor_sync(0xFFFFFFFFu, q, o);
        float rs = rsqrtf(q * (1.0f / HH) + 1e-5f);
        float4 g4 = __ldg(&((const float4*)gam)[lane]);
        float4 b4 = __ldg(&((const float4*)bet)[lane]);
        float4 o4;
        o4.x = fmaxf(dx * rs * g4.x + b4.x, 0.f);
        o4.y = fmaxf(dy * rs * g4.y + b4.y, 0.f);
        o4.z = fmaxf(dz * rs * g4.z + b4.z, 0.f);
        o4.w = fmaxf(dw * rs * g4.w + b4.w, 0.f);
        if (residual) {
            float4 h4 = ((const float4*)(in + (size_t)(m0 + m) * HH))[lane];
            o4.x += h4.x; o4.y += h4.y; o4.z += h4.z; o4.w += h4.w;
        }
        size_t rowo = (size_t)(m0 + m) * HH;
        ((float4*)(out + rowo))[lane] = o4;
        uint2 hpk;
        *(__half2*)&hpk.x = __floats2half2_rn(o4.x, o4.y);
        *(__half2*)&hpk.y = __floats2half2_rn(o4.z, o4.w);
        ((uint2*)(hh_out + rowo))[lane] = hpk;
    }
}

// ---------------- head: hidden = relu(h @ W1 + b1) in smem; out = hidden @ W2 + b2 ----------------
#define KC   16
#define LDSA 136
__global__ void __launch_bounds__(256) k_head(
    const float* __restrict__ A1,
    const float* __restrict__ W1, const float* __restrict__ b1,
    const float* __restrict__ W2, const float* __restrict__ b2,
    float* __restrict__ outp)
{
    extern __shared__ __align__(16) float sU[];      // SMEM_HEAD bytes (dynamic)
    __shared__ float sW2[HH * OUTD];
    __shared__ float sb2[OUTD];
    float (*Ah)[LDSA] = (float(*)[LDSA])sU;
    float (*Al)[LDSA] = (float(*)[LDSA])(sU + KC * LDSA);
    float (*Bh)[LDSA] = (float(*)[LDSA])(sU + 2 * KC * LDSA);
    float (*Bl)[LDSA] = (float(*)[LDSA])(sU + 3 * KC * LDSA);
    float* sC = sU;

    int tid  = threadIdx.x;
    int warp = tid >> 5, lane = tid & 31;
    int wm = warp & 1, wn = warp >> 1;
    int g  = lane >> 2, t = lane & 3;
    int m0 = blockIdx.x * 128;

    for (int i = tid; i < HH * OUTD; i += 256) sW2[i] = W2[i];
    if (tid < OUTD) sb2[tid] = b2[tid];

    float acc[4][4][4];
#pragma unroll
    for (int i = 0; i < 4; i++)
#pragma unroll
        for (int j = 0; j < 4; j++)
#pragma unroll
            for (int c = 0; c < 4; c++) acc[i][j][c] = 0.f;

    for (int kk = 0; kk < HH; kk += KC) {
        {
            int m   = tid >> 1;
            int kq0 = (tid & 1) * 8;
#pragma unroll
            for (int q = 0; q < 2; q++) {
                float4 v = *(const float4*)(A1 + (size_t)(m0 + m) * HH + kk + kq0 + q * 4);
                float e[4] = {v.x, v.y, v.z, v.w};
#pragma unroll
                for (int u = 0; u < 4; u++) {
                    float hi = tf32r(e[u]);
                    Ah[kq0 + q * 4 + u][m] = hi;
                    Al[kq0 + q * 4 + u][m] = tf32r(e[u] - hi);
                }
            }
        }
        {
            const float* Bp = W1 + (size_t)kk * HH;
            int kr  = tid >> 4;
            int cc0 = (tid & 15) * 8;
#pragma unroll
            for (int q = 0; q < 2; q++) {
                float4 v = *(const float4*)(Bp + (size_t)kr * HH + cc0 + q * 4);
                float e[4] = {v.x, v.y, v.z, v.w};
#pragma unroll
                for (int u = 0; u < 4; u++) {
                    float hi = tf32r(e[u]);
                    Bh[kr][cc0 + q * 4 + u] = hi;
                    Bl[kr][cc0 + q * 4 + u] = tf32r(e[u] - hi);
                }
            }
        }
        __syncthreads();

#pragma unroll
        for (int ks = 0; ks < KC / 8; ks++) {
            int k0 = ks * 8;
            uint32_t bh[4][2], bl[4][2];
#pragma unroll
            for (int ni = 0; ni < 4; ni++) {
                int nb = wn * 32 + ni * 8 + g;
                bh[ni][0] = __float_as_uint(Bh[k0 + t    ][nb]);
                bh[ni][1] = __float_as_uint(Bh[k0 + t + 4][nb]);
                bl[ni][0] = __float_as_uint(Bl[k0 + t    ][nb]);
                bl[ni][1] = __float_as_uint(Bl[k0 + t + 4][nb]);
            }
#pragma unroll
            for (int mi = 0; mi < 4; mi++) {
                int R = wm * 64 + mi * 16 + g;
                uint32_t ah0 = __float_as_uint(Ah[k0 + t    ][R]);
                uint32_t ah1 = __float_as_uint(Ah[k0 + t    ][R + 8]);
                uint32_t ah2 = __float_as_uint(Ah[k0 + t + 4][R]);
                uint32_t ah3 = __float_as_uint(Ah[k0 + t + 4][R + 8]);
                uint32_t al0 = __float_as_uint(Al[k0 + t    ][R]);
                uint32_t al1 = __float_as_uint(Al[k0 + t    ][R + 8]);
                uint32_t al2 = __float_as_uint(Al[k0 + t + 4][R]);
                uint32_t al3 = __float_as_uint(Al[k0 + t + 4][R + 8]);
#pragma unroll
                for (int ni = 0; ni < 4; ni++) {
                    float* c = acc[mi][ni];
                    mma_tf32(c[0], c[1], c[2], c[3], ah0, ah1, ah2, ah3, bh[ni][0], bh[ni][1]);
                    mma_tf32(c[0], c[1], c[2], c[3], ah0, ah1, ah2, ah3, bl[ni][0], bl[ni][1]);
                    mma_tf32(c[0], c[1], c[2], c[3], al0, al1, al2, al3, bh[ni][0], bh[ni][1]);
                }
            }
        }
        __syncthreads();
    }

    // hidden (bias + relu) -> sC
#pragma unroll
    for (int ni = 0; ni < 4; ni++) {
        int col = wn * 32 + ni * 8 + 2 * t;
        float b0 = b1[col], bb1 = b1[col + 1];
#pragma unroll
        for (int mi = 0; mi < 4; mi++) {
            int R = wm * 64 + mi * 16 + g;
            float* c = acc[mi][ni];
            sC[R * SCP + col]           = fmaxf(c[0] + b0, 0.f);
            sC[R * SCP + col + 1]       = fmaxf(c[1] + bb1, 0.f);
            sC[(R + 8) * SCP + col]     = fmaxf(c[2] + b0, 0.f);
            sC[(R + 8) * SCP + col + 1] = fmaxf(c[3] + bb1, 0.f);
        }
    }
    __syncthreads();

    // tail: out[row, 0..7] = hidden[row,:] @ W2 + b2
    {
        int row = tid >> 1;
        int cb  = (tid & 1) * 4;
        float o0 = sb2[cb], o1 = sb2[cb + 1], o2 = sb2[cb + 2], o3 = sb2[cb + 3];
#pragma unroll 4
        for (int k = 0; k < HH; k++) {
            float hv = sC[row * SCP + k];
            float4 w = *(const float4*)&sW2[k * OUTD + cb];
            o0 += hv * w.x; o1 += hv * w.y; o2 += hv * w.z; o3 += hv * w.w;
        }
        *(float4*)(outp + (size_t)(m0 + row) * OUTD + cb) = make_float4(o0, o1, o2, o3);
    }
}

// ---------------- launch ----------------
extern "C" void kernel_launch(void* const* d_in, const int* in_sizes, int n_in,
                              void* d_out, int out_size) {
    const float* x     = (const float*)d_in[0];
    const void*  ei    = d_in[1];
    const void*  et    = d_in[2];
    const float* W_in  = (const float*)d_in[3];
    const float* b_in  = (const float*)d_in[4];
    const float* basis = (const float*)d_in[5];
    const float* comp  = (const float*)d_in[6];
    const float* root  = (const float*)d_in[7];
    const float* bias  = (const float*)d_in[8];
    const float* ln_g  = (const float*)d_in[9];
    const float* ln_b  = (const float*)d_in[10];
    const float* W1    = (const float*)d_in[11];
    const float* b1    = (const float*)d_in[12];
    const float* W2    = (const float*)d_in[13];
    const float* b2    = (const float*)d_in[14];

    void *p_h, *p_t, *p_hh0, *p_hh1, *p_wB;
    cudaGetSymbolAddress(&p_h,   g_h);
    cudaGetSymbolAddress(&p_t,   g_t);
    cudaGetSymbolAddress(&p_hh0, g_hh0);
    cudaGetSymbolAddress(&p_hh1, g_hh1);
    cudaGetSymbolAddress(&p_wB,  g_wB);
    cudaFuncSetAttribute(k_layer, cudaFuncAttributeMaxDynamicSharedMemorySize, SMEM_LAYER);
    cudaFuncSetAttribute(k_head,  cudaFuncAttributeMaxDynamicSharedMemorySize, SMEM_HEAD);

    // ---- one-time preprocessing ----
    k_detect<<<1, 256>>>((const int*)ei);
    k_zero_cnt<<<(NN * RR + 255) / 256, 256>>>();
    k_prep_count<<<EE / 256, 256>>>(ei, et);
    k_ps1<<<NN / 256, 256>>>();
    k_ps2<<<1, 512>>>();
    k_ps3<<<NN / 256, 256>>>();
    k_csr_scatter<<<EE / 256, 256>>>();
    k_wconv<<<(LL * NCH * 128 * 16 + 255) / 256, 256>>>(basis, root);
    k_inproj<<<NN / 8, 128>>>(x, W_in, b_in);

    // ---- fused layers (ping-pong fp32 + fp16 mirrors) ----
    float*  bufs[2] = {(float*)p_h, (float*)p_t};
    __half* hhb[2]  = {(__half*)p_hh0, (__half*)p_hh1};
    for (int i = 0; i < LL; i++) {
        k_layer<<<NN / TM, 256, SMEM_LAYER>>>(
            bufs[i & 1], bufs[(i + 1) & 1],
            hhb[i & 1], hhb[(i + 1) & 1],
            (const __half*)p_wB + (size_t)i * NCH * 128 * 16,
            comp + i * RR * BB,
            bias + i * HH, ln_g + i * HH, ln_b + i * HH, i > 0 ? 1 : 0);
    }

    // ---- fused head ----
    k_head<<<NN / 128, 256, SMEM_HEAD>>>(bufs[LL & 1], W1, b1, W2, b2, (float*)d_out);
}